// round 1
// baseline (speedup 1.0000x reference)
#include <cuda_runtime.h>
#include <cstdint>

#define Bb   8
#define Ll   4096
#define Dd   1024
#define Hh   16
#define DHh  64
#define FFD  4096
#define Mrows (Bb*Ll)          // 32768
#define NE   (Mrows*Dd)        // 33554432
#define NEFF (Mrows*FFD)       // 134217728

// ---------------- scratch (static device globals; allowed) ----------------
__device__ float g_xp[NE];    // X + pe
__device__ float g_q[NE];
__device__ float g_k[NE];
__device__ float g_v[NE];
__device__ float g_ctx[NE];
__device__ float g_x1[NE];    // post-LN1
__device__ float g_y1[NE];    // pre-LN scratch (reused for both LNs)
__device__ float g_h[NEFF];   // FFN hidden

// ---------------- X + pe ----------------
__global__ __launch_bounds__(256) void addpe_kernel(
    const float* __restrict__ X, const float* __restrict__ pe, float* __restrict__ Xp)
{
    const size_t n4  = (size_t)NE / 4;
    const size_t pe4 = (size_t)Ll * Dd / 4;
    for (size_t i = (size_t)blockIdx.x * blockDim.x + threadIdx.x; i < n4;
         i += (size_t)gridDim.x * blockDim.x) {
        float4 a = ((const float4*)X)[i];
        float4 p = ((const float4*)pe)[i % pe4];
        a.x += p.x; a.y += p.y; a.z += p.z; a.w += p.w;
        ((float4*)Xp)[i] = a;
    }
}

// ---------------- SGEMM: C[M,N] = A[M,K] @ W[K,N] + bias (+R) (+relu) ------
// BM=BN=128, BK=16, 256 threads, 8x8 per thread (split 4+4 to avoid conflicts)
#define BK 16
__global__ __launch_bounds__(256) void gemm_kernel(
    const float* __restrict__ A, const float* __restrict__ W,
    const float* __restrict__ bias, const float* __restrict__ R,
    float* __restrict__ C, int K, int N, int doRelu)
{
    __shared__ float As[BK][128];
    __shared__ float Ws[BK][128];

    const int tid = threadIdx.x;
    const int m0 = blockIdx.y * 128;
    const int n0 = blockIdx.x * 128;
    const int tx = tid & 15;          // 0..15
    const int ty = tid >> 4;          // 0..15

    float acc[8][8];
#pragma unroll
    for (int i = 0; i < 8; i++)
#pragma unroll
        for (int j = 0; j < 8; j++) acc[i][j] = 0.f;

    const int arow = tid >> 2;        // 0..63
    const int aks  = (tid & 3) * 4;   // 0,4,8,12
    const int wkr  = tid >> 5;        // 0..7
    const int wns  = (tid & 31) * 4;  // 0..124

    for (int k0 = 0; k0 < K; k0 += BK) {
        // load A tile (128 x 16), store transposed
        float4 a0 = *(const float4*)&A[(size_t)(m0 + arow)      * K + k0 + aks];
        float4 a1 = *(const float4*)&A[(size_t)(m0 + arow + 64) * K + k0 + aks];
        As[aks + 0][arow] = a0.x; As[aks + 1][arow] = a0.y;
        As[aks + 2][arow] = a0.z; As[aks + 3][arow] = a0.w;
        As[aks + 0][arow + 64] = a1.x; As[aks + 1][arow + 64] = a1.y;
        As[aks + 2][arow + 64] = a1.z; As[aks + 3][arow + 64] = a1.w;
        // load W tile (16 x 128)
        *(float4*)&Ws[wkr    ][wns] = *(const float4*)&W[(size_t)(k0 + wkr    ) * N + n0 + wns];
        *(float4*)&Ws[wkr + 8][wns] = *(const float4*)&W[(size_t)(k0 + wkr + 8) * N + n0 + wns];
        __syncthreads();

#pragma unroll
        for (int kk = 0; kk < BK; kk++) {
            float ra[8], rb[8];
            *(float4*)&ra[0] = *(const float4*)&As[kk][ty * 4];
            *(float4*)&ra[4] = *(const float4*)&As[kk][64 + ty * 4];
            *(float4*)&rb[0] = *(const float4*)&Ws[kk][tx * 4];
            *(float4*)&rb[4] = *(const float4*)&Ws[kk][64 + tx * 4];
#pragma unroll
            for (int i = 0; i < 8; i++)
#pragma unroll
                for (int j = 0; j < 8; j++) acc[i][j] += ra[i] * rb[j];
        }
        __syncthreads();
    }

#pragma unroll
    for (int i = 0; i < 8; i++) {
        const int r = m0 + ((i < 4) ? (ty * 4 + i) : (64 + ty * 4 + (i - 4)));
#pragma unroll
        for (int js = 0; js < 2; js++) {
            const int c = n0 + js * 64 + tx * 4;
            float4 o;
            o.x = acc[i][js * 4 + 0] + bias[c + 0];
            o.y = acc[i][js * 4 + 1] + bias[c + 1];
            o.z = acc[i][js * 4 + 2] + bias[c + 2];
            o.w = acc[i][js * 4 + 3] + bias[c + 3];
            if (R) {
                float4 rr = *(const float4*)&R[(size_t)r * N + c];
                o.x += rr.x; o.y += rr.y; o.z += rr.z; o.w += rr.w;
            }
            if (doRelu) {
                o.x = fmaxf(o.x, 0.f); o.y = fmaxf(o.y, 0.f);
                o.z = fmaxf(o.z, 0.f); o.w = fmaxf(o.w, 0.f);
            }
            *(float4*)&C[(size_t)r * N + c] = o;
        }
    }
}

// ---------------- window-3 attention: one warp per (b,l,h) ----------------
__global__ __launch_bounds__(512) void attn_kernel(
    const float* __restrict__ q, const float* __restrict__ k,
    const float* __restrict__ v, const unsigned char* __restrict__ mask,
    float* __restrict__ ctx)
{
    const int bl   = blockIdx.x;            // b*L + l
    const int b    = bl >> 12;
    const int l    = bl & 4095;
    const int wid  = threadIdx.x >> 5;      // head
    const int lane = threadIdx.x & 31;

    const size_t base = (size_t)bl * Dd + wid * DHh;
    const float q0 = q[base + lane];
    const float q1 = q[base + lane + 32];

    float sc[3];
    int   lks[3];
#pragma unroll
    for (int w = 0; w < 3; w++) {
        int lk = l + w - 1;
        bool inb = (lk >= 0) && (lk < Ll);
        int lkc = lk < 0 ? 0 : (lk > Ll - 1 ? Ll - 1 : lk);
        lks[w] = lkc;
        bool ok = inb && (mask[(b << 12) + lkc] == 0);
        const size_t kb = ((size_t)(b << 12) + lkc) * Dd + wid * DHh;
        float d = q0 * k[kb + lane] + q1 * k[kb + lane + 32];
#pragma unroll
        for (int o = 16; o; o >>= 1) d += __shfl_xor_sync(0xffffffffu, d, o);
        sc[w] = ok ? d * 0.125f : -1e30f;
    }
    float m  = fmaxf(sc[0], fmaxf(sc[1], sc[2]));
    float e0 = expf(sc[0] - m), e1 = expf(sc[1] - m), e2 = expf(sc[2] - m);
    float inv = 1.f / (e0 + e1 + e2);
    float a0 = e0 * inv, a1 = e1 * inv, a2 = e2 * inv;

    float c0 = 0.f, c1 = 0.f;
    {
        const size_t vb = ((size_t)(b << 12) + lks[0]) * Dd + wid * DHh;
        c0 += a0 * v[vb + lane]; c1 += a0 * v[vb + lane + 32];
    }
    {
        const size_t vb = ((size_t)(b << 12) + lks[1]) * Dd + wid * DHh;
        c0 += a1 * v[vb + lane]; c1 += a1 * v[vb + lane + 32];
    }
    {
        const size_t vb = ((size_t)(b << 12) + lks[2]) * Dd + wid * DHh;
        c0 += a2 * v[vb + lane]; c1 += a2 * v[vb + lane + 32];
    }
    ctx[base + lane]      = c0;
    ctx[base + lane + 32] = c1;
}

// ---------------- LayerNorm over D=1024, one block per row ----------------
__global__ __launch_bounds__(256) void ln_kernel(
    const float* __restrict__ X, const float* __restrict__ gam,
    const float* __restrict__ bet, float* __restrict__ Y)
{
    const int row = blockIdx.x;
    const int tid = threadIdx.x;
    float4 vv = ((const float4*)(X + (size_t)row * Dd))[tid];
    float s  = vv.x + vv.y + vv.z + vv.w;
    float ss = vv.x * vv.x + vv.y * vv.y + vv.z * vv.z + vv.w * vv.w;
#pragma unroll
    for (int o = 16; o; o >>= 1) {
        s  += __shfl_xor_sync(0xffffffffu, s,  o);
        ss += __shfl_xor_sync(0xffffffffu, ss, o);
    }
    __shared__ float sh_s[8], sh_ss[8];
    const int w = tid >> 5, lane = tid & 31;
    if (lane == 0) { sh_s[w] = s; sh_ss[w] = ss; }
    __syncthreads();
    s = 0.f; ss = 0.f;
#pragma unroll
    for (int i = 0; i < 8; i++) { s += sh_s[i]; ss += sh_ss[i]; }
    const float mean = s * (1.f / Dd);
    const float var  = ss * (1.f / Dd) - mean * mean;
    const float rstd = rsqrtf(var + 1e-5f);
    float4 g4 = ((const float4*)gam)[tid];
    float4 b4 = ((const float4*)bet)[tid];
    float4 o;
    o.x = (vv.x - mean) * rstd * g4.x + b4.x;
    o.y = (vv.y - mean) * rstd * g4.y + b4.y;
    o.z = (vv.z - mean) * rstd * g4.z + b4.z;
    o.w = (vv.w - mean) * rstd * g4.w + b4.w;
    ((float4*)(Y + (size_t)row * Dd))[tid] = o;
}

// ---------------- launcher ----------------
extern "C" void kernel_launch(void* const* d_in, const int* in_sizes, int n_in,
                              void* d_out, int out_size)
{
    const float* X    = (const float*)d_in[0];
    const unsigned char* mask = (const unsigned char*)d_in[1];
    const float* pe   = (const float*)d_in[2];
    const float* Wq   = (const float*)d_in[3];
    const float* Wk   = (const float*)d_in[4];
    const float* Wv   = (const float*)d_in[5];
    const float* bq   = (const float*)d_in[6];
    const float* bk   = (const float*)d_in[7];
    const float* bv   = (const float*)d_in[8];
    const float* Wo   = (const float*)d_in[9];
    const float* bo   = (const float*)d_in[10];
    const float* g1   = (const float*)d_in[11];
    const float* be1  = (const float*)d_in[12];
    const float* W1   = (const float*)d_in[13];
    const float* b1   = (const float*)d_in[14];
    const float* W2   = (const float*)d_in[15];
    const float* b2   = (const float*)d_in[16];
    const float* g2   = (const float*)d_in[17];
    const float* be2  = (const float*)d_in[18];
    float* out = (float*)d_out;

    float *xp, *q, *k, *v, *ctx, *x1, *y1, *hbuf;
    cudaGetSymbolAddress((void**)&xp,  g_xp);
    cudaGetSymbolAddress((void**)&q,   g_q);
    cudaGetSymbolAddress((void**)&k,   g_k);
    cudaGetSymbolAddress((void**)&v,   g_v);
    cudaGetSymbolAddress((void**)&ctx, g_ctx);
    cudaGetSymbolAddress((void**)&x1,  g_x1);
    cudaGetSymbolAddress((void**)&y1,  g_y1);
    cudaGetSymbolAddress((void**)&hbuf,g_h);

    addpe_kernel<<<8192, 256>>>(X, pe, xp);

    dim3 gDD(Dd / 128, Mrows / 128);     // (8, 256)
    dim3 gDF(FFD / 128, Mrows / 128);    // (32, 256)

    gemm_kernel<<<gDD, 256>>>(xp, Wq, bq, nullptr, q, Dd, Dd, 0);
    gemm_kernel<<<gDD, 256>>>(xp, Wk, bk, nullptr, k, Dd, Dd, 0);
    gemm_kernel<<<gDD, 256>>>(xp, Wv, bv, nullptr, v, Dd, Dd, 0);

    attn_kernel<<<Mrows, 512>>>(q, k, v, mask, ctx);

    gemm_kernel<<<gDD, 256>>>(ctx, Wo, bo, xp, y1, Dd, Dd, 0);   // + residual (X+pe)
    ln_kernel<<<Mrows, 256>>>(y1, g1, be1, x1);

    gemm_kernel<<<gDF, 256>>>(x1, W1, b1, nullptr, hbuf, Dd, FFD, 1);   // ReLU
    gemm_kernel<<<gDD, 256>>>(hbuf, W2, b2, x1, y1, FFD, Dd, 0);        // + residual
    ln_kernel<<<Mrows, 256>>>(y1, g2, be2, out);
}

// round 2
// speedup vs baseline: 1.0056x; 1.0056x over previous
#include <cuda_runtime.h>
#include <cstdint>

#define Bb   8
#define Ll   4096
#define Dd   1024
#define Hh   16
#define DHh  64
#define FFD  4096
#define Mrows (Bb*Ll)          // 32768
#define NE   (Mrows*Dd)        // 33554432
#define NEFF (Mrows*FFD)       // 134217728

// ---------------- scratch (static device globals; allowed) ----------------
__device__ float g_xp[NE];    // X + pe
__device__ float g_q[NE];
__device__ float g_k[NE];
__device__ float g_v[NE];
__device__ float g_ctx[NE];
__device__ float g_x1[NE];    // post-LN1
__device__ float g_y1[NE];    // pre-LN scratch (reused for both LNs)
__device__ float g_h[NEFF];   // FFN hidden

// ---------------- X + pe ----------------
__global__ __launch_bounds__(256) void addpe_kernel(
    const float* __restrict__ X, const float* __restrict__ pe, float* __restrict__ Xp)
{
    const size_t n4  = (size_t)NE / 4;
    const size_t pe4 = (size_t)Ll * Dd / 4;
    for (size_t i = (size_t)blockIdx.x * blockDim.x + threadIdx.x; i < n4;
         i += (size_t)gridDim.x * blockDim.x) {
        float4 a = ((const float4*)X)[i];
        float4 p = ((const float4*)pe)[i % pe4];
        a.x += p.x; a.y += p.y; a.z += p.z; a.w += p.w;
        ((float4*)Xp)[i] = a;
    }
}

// ---------------- SGEMM: C[M,N] = A[M,K] @ W[K,N] + bias (+R) (+relu) ------
// BM=BN=128, BK=16, 256 threads, 8x8 per thread (split 4+4 to avoid conflicts)
#define BK 16
__global__ __launch_bounds__(256) void gemm_kernel(
    const float* __restrict__ A, const float* __restrict__ W,
    const float* __restrict__ bias, const float* __restrict__ R,
    float* __restrict__ C, int K, int N, int doRelu)
{
    __shared__ float As[BK][128];
    __shared__ float Ws[BK][128];

    const int tid = threadIdx.x;
    const int m0 = blockIdx.y * 128;
    const int n0 = blockIdx.x * 128;
    const int tx = tid & 15;          // 0..15
    const int ty = tid >> 4;          // 0..15

    float acc[8][8];
#pragma unroll
    for (int i = 0; i < 8; i++)
#pragma unroll
        for (int j = 0; j < 8; j++) acc[i][j] = 0.f;

    const int arow = tid >> 2;        // 0..63
    const int aks  = (tid & 3) * 4;   // 0,4,8,12
    const int wkr  = tid >> 5;        // 0..7
    const int wns  = (tid & 31) * 4;  // 0..124

    for (int k0 = 0; k0 < K; k0 += BK) {
        // load A tile (128 x 16), store transposed
        float4 a0 = *(const float4*)&A[(size_t)(m0 + arow)      * K + k0 + aks];
        float4 a1 = *(const float4*)&A[(size_t)(m0 + arow + 64) * K + k0 + aks];
        As[aks + 0][arow] = a0.x; As[aks + 1][arow] = a0.y;
        As[aks + 2][arow] = a0.z; As[aks + 3][arow] = a0.w;
        As[aks + 0][arow + 64] = a1.x; As[aks + 1][arow + 64] = a1.y;
        As[aks + 2][arow + 64] = a1.z; As[aks + 3][arow + 64] = a1.w;
        // load W tile (16 x 128)
        *(float4*)&Ws[wkr    ][wns] = *(const float4*)&W[(size_t)(k0 + wkr    ) * N + n0 + wns];
        *(float4*)&Ws[wkr + 8][wns] = *(const float4*)&W[(size_t)(k0 + wkr + 8) * N + n0 + wns];
        __syncthreads();

#pragma unroll
        for (int kk = 0; kk < BK; kk++) {
            float ra[8], rb[8];
            *(float4*)&ra[0] = *(const float4*)&As[kk][ty * 4];
            *(float4*)&ra[4] = *(const float4*)&As[kk][64 + ty * 4];
            *(float4*)&rb[0] = *(const float4*)&Ws[kk][tx * 4];
            *(float4*)&rb[4] = *(const float4*)&Ws[kk][64 + tx * 4];
#pragma unroll
            for (int i = 0; i < 8; i++)
#pragma unroll
                for (int j = 0; j < 8; j++) acc[i][j] += ra[i] * rb[j];
        }
        __syncthreads();
    }

#pragma unroll
    for (int i = 0; i < 8; i++) {
        const int r = m0 + ((i < 4) ? (ty * 4 + i) : (64 + ty * 4 + (i - 4)));
#pragma unroll
        for (int js = 0; js < 2; js++) {
            const int c = n0 + js * 64 + tx * 4;
            float4 o;
            o.x = acc[i][js * 4 + 0] + bias[c + 0];
            o.y = acc[i][js * 4 + 1] + bias[c + 1];
            o.z = acc[i][js * 4 + 2] + bias[c + 2];
            o.w = acc[i][js * 4 + 3] + bias[c + 3];
            if (R) {
                float4 rr = *(const float4*)&R[(size_t)r * N + c];
                o.x += rr.x; o.y += rr.y; o.z += rr.z; o.w += rr.w;
            }
            if (doRelu) {
                o.x = fmaxf(o.x, 0.f); o.y = fmaxf(o.y, 0.f);
                o.z = fmaxf(o.z, 0.f); o.w = fmaxf(o.w, 0.f);
            }
            *(float4*)&C[(size_t)r * N + c] = o;
        }
    }
}

// ---------------- window-3 attention: one warp per (b,l,h) ----------------
__global__ __launch_bounds__(512) void attn_kernel(
    const float* __restrict__ q, const float* __restrict__ k,
    const float* __restrict__ v, const unsigned char* __restrict__ mask,
    float* __restrict__ ctx)
{
    const int bl   = blockIdx.x;            // b*L + l
    const int b    = bl >> 12;
    const int l    = bl & 4095;
    const int wid  = threadIdx.x >> 5;      // head
    const int lane = threadIdx.x & 31;

    const size_t base = (size_t)bl * Dd + wid * DHh;
    const float q0 = q[base + lane];
    const float q1 = q[base + lane + 32];

    float sc[3];
    int   lks[3];
#pragma unroll
    for (int w = 0; w < 3; w++) {
        int lk = l + w - 1;
        bool inb = (lk >= 0) && (lk < Ll);
        int lkc = lk < 0 ? 0 : (lk > Ll - 1 ? Ll - 1 : lk);
        lks[w] = lkc;
        bool ok = inb && (mask[(b << 12) + lkc] == 0);
        const size_t kb = ((size_t)(b << 12) + lkc) * Dd + wid * DHh;
        float d = q0 * k[kb + lane] + q1 * k[kb + lane + 32];
#pragma unroll
        for (int o = 16; o; o >>= 1) d += __shfl_xor_sync(0xffffffffu, d, o);
        sc[w] = ok ? d * 0.125f : -1e30f;
    }
    float m  = fmaxf(sc[0], fmaxf(sc[1], sc[2]));
    float e0 = expf(sc[0] - m), e1 = expf(sc[1] - m), e2 = expf(sc[2] - m);
    float inv = 1.f / (e0 + e1 + e2);
    float a0 = e0 * inv, a1 = e1 * inv, a2 = e2 * inv;

    float c0 = 0.f, c1 = 0.f;
    {
        const size_t vb = ((size_t)(b << 12) + lks[0]) * Dd + wid * DHh;
        c0 += a0 * v[vb + lane]; c1 += a0 * v[vb + lane + 32];
    }
    {
        const size_t vb = ((size_t)(b << 12) + lks[1]) * Dd + wid * DHh;
        c0 += a1 * v[vb + lane]; c1 += a1 * v[vb + lane + 32];
    }
    {
        const size_t vb = ((size_t)(b << 12) + lks[2]) * Dd + wid * DHh;
        c0 += a2 * v[vb + lane]; c1 += a2 * v[vb + lane + 32];
    }
    ctx[base + lane]      = c0;
    ctx[base + lane + 32] = c1;
}

// ---------------- LayerNorm over D=1024, one block per row ----------------
__global__ __launch_bounds__(256) void ln_kernel(
    const float* __restrict__ X, const float* __restrict__ gam,
    const float* __restrict__ bet, float* __restrict__ Y)
{
    const int row = blockIdx.x;
    const int tid = threadIdx.x;
    float4 vv = ((const float4*)(X + (size_t)row * Dd))[tid];
    float s  = vv.x + vv.y + vv.z + vv.w;
    float ss = vv.x * vv.x + vv.y * vv.y + vv.z * vv.z + vv.w * vv.w;
#pragma unroll
    for (int o = 16; o; o >>= 1) {
        s  += __shfl_xor_sync(0xffffffffu, s,  o);
        ss += __shfl_xor_sync(0xffffffffu, ss, o);
    }
    __shared__ float sh_s[8], sh_ss[8];
    const int w = tid >> 5, lane = tid & 31;
    if (lane == 0) { sh_s[w] = s; sh_ss[w] = ss; }
    __syncthreads();
    s = 0.f; ss = 0.f;
#pragma unroll
    for (int i = 0; i < 8; i++) { s += sh_s[i]; ss += sh_ss[i]; }
    const float mean = s * (1.f / Dd);
    const float var  = ss * (1.f / Dd) - mean * mean;
    const float rstd = rsqrtf(var + 1e-5f);
    float4 g4 = ((const float4*)gam)[tid];
    float4 b4 = ((const float4*)bet)[tid];
    float4 o;
    o.x = (vv.x - mean) * rstd * g4.x + b4.x;
    o.y = (vv.y - mean) * rstd * g4.y + b4.y;
    o.z = (vv.z - mean) * rstd * g4.z + b4.z;
    o.w = (vv.w - mean) * rstd * g4.w + b4.w;
    ((float4*)(Y + (size_t)row * Dd))[tid] = o;
}

// ---------------- launcher ----------------
extern "C" void kernel_launch(void* const* d_in, const int* in_sizes, int n_in,
                              void* d_out, int out_size)
{
    const float* X    = (const float*)d_in[0];
    const unsigned char* mask = (const unsigned char*)d_in[1];
    const float* pe   = (const float*)d_in[2];
    const float* Wq   = (const float*)d_in[3];
    const float* Wk   = (const float*)d_in[4];
    const float* Wv   = (const float*)d_in[5];
    const float* bq   = (const float*)d_in[6];
    const float* bk   = (const float*)d_in[7];
    const float* bv   = (const float*)d_in[8];
    const float* Wo   = (const float*)d_in[9];
    const float* bo   = (const float*)d_in[10];
    const float* g1   = (const float*)d_in[11];
    const float* be1  = (const float*)d_in[12];
    const float* W1   = (const float*)d_in[13];
    const float* b1   = (const float*)d_in[14];
    const float* W2   = (const float*)d_in[15];
    const float* b2   = (const float*)d_in[16];
    const float* g2   = (const float*)d_in[17];
    const float* be2  = (const float*)d_in[18];
    float* out = (float*)d_out;

    float *xp, *q, *k, *v, *ctx, *x1, *y1, *hbuf;
    cudaGetSymbolAddress((void**)&xp,  g_xp);
    cudaGetSymbolAddress((void**)&q,   g_q);
    cudaGetSymbolAddress((void**)&k,   g_k);
    cudaGetSymbolAddress((void**)&v,   g_v);
    cudaGetSymbolAddress((void**)&ctx, g_ctx);
    cudaGetSymbolAddress((void**)&x1,  g_x1);
    cudaGetSymbolAddress((void**)&y1,  g_y1);
    cudaGetSymbolAddress((void**)&hbuf,g_h);

    addpe_kernel<<<8192, 256>>>(X, pe, xp);

    dim3 gDD(Dd / 128, Mrows / 128);     // (8, 256)
    dim3 gDF(FFD / 128, Mrows / 128);    // (32, 256)

    gemm_kernel<<<gDD, 256>>>(xp, Wq, bq, nullptr, q, Dd, Dd, 0);
    gemm_kernel<<<gDD, 256>>>(xp, Wk, bk, nullptr, k, Dd, Dd, 0);
    gemm_kernel<<<gDD, 256>>>(xp, Wv, bv, nullptr, v, Dd, Dd, 0);

    attn_kernel<<<Mrows, 512>>>(q, k, v, mask, ctx);

    gemm_kernel<<<gDD, 256>>>(ctx, Wo, bo, xp, y1, Dd, Dd, 0);   // + residual (X+pe)
    ln_kernel<<<Mrows, 256>>>(y1, g1, be1, x1);

    gemm_kernel<<<gDF, 256>>>(x1, W1, b1, nullptr, hbuf, Dd, FFD, 1);   // ReLU
    gemm_kernel<<<gDD, 256>>>(hbuf, W2, b2, x1, y1, FFD, Dd, 0);        // + residual
    ln_kernel<<<Mrows, 256>>>(y1, g2, be2, out);
}

// round 6
// speedup vs baseline: 3.0163x; 2.9996x over previous
#include <cuda_runtime.h>
#include <cuda_bf16.h>
#include <cstdint>

#define Bb 8
#define Ll 4096
#define Dd 1024
#define FFD 4096
#define Mrows (Bb*Ll)
#define NE   (Mrows*Dd)
#define NEFF (Mrows*FFD)

__device__ float g_xp[NE], g_q[NE], g_k[NE], g_v[NE], g_y1[NE], g_x1[NE];
__device__ __nv_bfloat16 g_xph[NE], g_xpl[NE], g_ch[NE], g_cl[NE], g_x1h[NE], g_x1l[NE];
__device__ __nv_bfloat16 g_hh[NEFF], g_hl[NEFF];
__device__ __nv_bfloat16 g_wqh[Dd*Dd], g_wql[Dd*Dd], g_wkh[Dd*Dd], g_wkl[Dd*Dd];
__device__ __nv_bfloat16 g_wvh[Dd*Dd], g_wvl[Dd*Dd], g_woh[Dd*Dd], g_wol[Dd*Dd];
__device__ __nv_bfloat16 g_w1h[Dd*FFD], g_w1l[Dd*FFD], g_w2h[FFD*Dd], g_w2l[FFD*Dd];

__device__ __forceinline__ uint32_t smem_u32(const void* p){
    uint32_t a; asm("{ .reg .u64 t; cvta.to.shared.u64 t, %1; cvt.u32.u64 %0, t; }":"=r"(a):"l"(p)); return a;
}
__device__ __forceinline__ void bsplit(float v, __nv_bfloat16& h, __nv_bfloat16& l){
    h = __float2bfloat16(v); l = __float2bfloat16(v - __bfloat162float(h));
}
__device__ __forceinline__ uint32_t pack2(__nv_bfloat16 a, __nv_bfloat16 b){
    return (uint32_t)__bfloat16_as_ushort(a) | ((uint32_t)__bfloat16_as_ushort(b) << 16);
}

#define LDSM4(r0,r1,r2,r3,ad) \
    asm volatile("ldmatrix.sync.aligned.m8n8.x4.shared.b16 {%0,%1,%2,%3}, [%4];" \
        : "=r"(r0),"=r"(r1),"=r"(r2),"=r"(r3) : "r"(ad))

#define MMA16816(d,a0,a1,a2,a3,b0,b1) \
    asm volatile("mma.sync.aligned.m16n8k16.row.col.f32.bf16.bf16.f32 " \
        "{%0,%1,%2,%3},{%4,%5,%6,%7},{%8,%9},{%0,%1,%2,%3};" \
        : "+f"((d)[0]),"+f"((d)[1]),"+f"((d)[2]),"+f"((d)[3]) \
        : "r"(a0),"r"(a1),"r"(a2),"r"(a3),"r"(b0),"r"(b1))

#define CPA16(sd,gp) asm volatile("cp.async.cg.shared.global [%0], [%1], 16;"::"r"(sd),"l"(gp):"memory")

__global__ __launch_bounds__(256) void addpe_split(
    const float* __restrict__ X, const float* __restrict__ pe,
    float* __restrict__ xp, __nv_bfloat16* __restrict__ xh, __nv_bfloat16* __restrict__ xl)
{
    const size_t n4 = (size_t)NE/4, pe4 = (size_t)Ll*Dd/4;
    for (size_t i = (size_t)blockIdx.x*blockDim.x+threadIdx.x; i < n4; i += (size_t)gridDim.x*blockDim.x){
        float4 a = ((const float4*)X)[i]; float4 p = ((const float4*)pe)[i % pe4];
        a.x+=p.x; a.y+=p.y; a.z+=p.z; a.w+=p.w;
        ((float4*)xp)[i] = a;
        __nv_bfloat16 h0,l0,h1,l1,h2,l2,h3,l3;
        bsplit(a.x,h0,l0); bsplit(a.y,h1,l1); bsplit(a.z,h2,l2); bsplit(a.w,h3,l3);
        ((uint32_t*)xh)[i*2]=pack2(h0,h1); ((uint32_t*)xh)[i*2+1]=pack2(h2,h3);
        ((uint32_t*)xl)[i*2]=pack2(l0,l1); ((uint32_t*)xl)[i*2+1]=pack2(l2,l3);
    }
}

__global__ __launch_bounds__(256) void wtrans(
    const float* __restrict__ W, int K, int N,
    __nv_bfloat16* __restrict__ Th, __nv_bfloat16* __restrict__ Tl)
{
    __shared__ float t[32][33];
    const int bn = blockIdx.x*32, bk = blockIdx.y*32;
    const int tx = threadIdx.x&31, ty = threadIdx.x>>5;
#pragma unroll
    for (int r = 0; r < 32; r += 8) t[ty+r][tx] = W[(size_t)(bk+ty+r)*N + bn+tx];
    __syncthreads();
#pragma unroll
    for (int r = 0; r < 32; r += 8){
        float v = t[tx][ty+r];
        __nv_bfloat16 h,l; bsplit(v,h,l);
        size_t o = (size_t)(bn+ty+r)*K + bk+tx;
        Th[o]=h; Tl[o]=l;
    }
}

// ---- HMMA GEMM: D[M,N] = A[M,K] @ T[N,K]^T, 3-pass bf16 split ----
// BM=128 BN=128 BK=64(bf16), 3 stages, 256 thr (8 warps, 2m x 4n, warp 64x32)
#define STAGES 3
#define STGB 32768

__device__ __forceinline__ void load_op(uint32_t sdst, const __nv_bfloat16* __restrict__ g,
                                        int ldk, int row0, int k0, int tid)
{
    const __nv_bfloat16* gb = g + (size_t)row0*ldk + k0;
#pragma unroll
    for (int t = 0; t < 4; ++t){
        int idx = t*256 + tid;          // 1024 chunks of 16B
        int row = idx >> 3, j = idx & 7;
        uint32_t so = (uint32_t)row*128u + (((uint32_t)j*16u) ^ (((uint32_t)row&7u)*16u));
        CPA16(sdst + so, gb + (size_t)row*ldk + j*8);
    }
}

// mode 0: bias->Cf ; 1: bias+R->Cf ; 2: relu(bias)->split Ch/Cl
__global__ void __launch_bounds__(256) tgemm(
    const __nv_bfloat16* __restrict__ Ah, const __nv_bfloat16* __restrict__ Al,
    const __nv_bfloat16* __restrict__ Bh, const __nv_bfloat16* __restrict__ Bl,
    const float* __restrict__ bias, const float* __restrict__ Rres,
    float* __restrict__ Cf, __nv_bfloat16* __restrict__ Ch, __nv_bfloat16* __restrict__ Cl,
    int K, int N, int mode)
{
    extern __shared__ char smem[];
    const uint32_t sb = smem_u32(smem);
    const int tid = threadIdx.x, wid = tid>>5, lane = tid&31;
    const int wm = wid & 1, wn = wid >> 1;
    const int m0 = blockIdx.y*128, n0 = blockIdx.x*128;

    const __nv_bfloat16* APs[3] = {Ah, Ah, Al};
    const __nv_bfloat16* BPs[3] = {Bh, Bl, Bh};
    const int kpass = K >> 6, T = 3*kpass;

    float acc[4][4][4];
#pragma unroll
    for (int a=0;a<4;a++)
#pragma unroll
    for (int b=0;b<4;b++)
#pragma unroll
    for (int c=0;c<4;c++) acc[a][b][c]=0.f;

#pragma unroll
    for (int it = 0; it < STAGES-1; ++it){
        int p = it/kpass, kk = (it - p*kpass)*64;
        load_op(sb + it*STGB,          APs[p], K, m0, kk, tid);
        load_op(sb + it*STGB + 16384,  BPs[p], K, n0, kk, tid);
        asm volatile("cp.async.commit_group;":::"memory");
    }

    const int r16 = lane & 15, cg = lane >> 4;
    for (int it = 0; it < T; ++it){
        if (it == T-1) asm volatile("cp.async.wait_group 0;":::"memory");
        else           asm volatile("cp.async.wait_group %0;"::"n"(STAGES-2):"memory");
        __syncthreads();
        if (it + STAGES-1 < T){
            const int it2 = it + STAGES-1, p = it2/kpass, kk = (it2 - p*kpass)*64;
            const uint32_t slot = sb + (it2 % STAGES)*STGB;
            load_op(slot,         APs[p], K, m0, kk, tid);
            load_op(slot + 16384, BPs[p], K, n0, kk, tid);
            asm volatile("cp.async.commit_group;":::"memory");
        }
        const uint32_t sA = sb + (it % STAGES)*STGB, sB = sA + 16384u;
#pragma unroll
        for (int kk = 0; kk < 4; ++kk){
            const uint32_t col = (uint32_t)kk*32u + (uint32_t)cg*16u;
            uint32_t a[4][4], bfr[2][4];
#pragma unroll
            for (int mi = 0; mi < 4; ++mi){
                int row = wm*64 + mi*16 + r16;
                uint32_t ad = sA + (uint32_t)row*128u + (col ^ (((uint32_t)row&7u)*16u));
                LDSM4(a[mi][0],a[mi][1],a[mi][2],a[mi][3], ad);
            }
#pragma unroll
            for (int nb = 0; nb < 2; ++nb){
                int row = wn*32 + nb*16 + r16;
                uint32_t ad = sB + (uint32_t)row*128u + (col ^ (((uint32_t)row&7u)*16u));
                LDSM4(bfr[nb][0],bfr[nb][1],bfr[nb][2],bfr[nb][3], ad);
            }
#pragma unroll
            for (int mi = 0; mi < 4; ++mi)
#pragma unroll
                for (int nj = 0; nj < 4; ++nj){
                    const int nb = nj>>1, hf = nj&1;
                    MMA16816(acc[mi][nj], a[mi][0],a[mi][1],a[mi][2],a[mi][3],
                             bfr[nb][hf], bfr[nb][hf+2]);
                }
        }
        __syncthreads();
    }

    // ---- epilogue ----
    const int mwb = m0 + wm*64, nwb = n0 + wn*32;
#pragma unroll
    for (int mi = 0; mi < 4; ++mi)
#pragma unroll
    for (int nj = 0; nj < 4; ++nj){
        const int col = nwb + nj*8 + (lane&3)*2;
        const float2 bb = *(const float2*)&bias[col];
#pragma unroll
        for (int h = 0; h < 2; ++h){
            const int row = mwb + mi*16 + (lane>>2) + h*8;
            float x0 = acc[mi][nj][h*2+0] + bb.x;
            float x1 = acc[mi][nj][h*2+1] + bb.y;
            if (mode == 1){
                float2 rr = *(const float2*)&Rres[(size_t)row*N + col];
                x0 += rr.x; x1 += rr.y;
            }
            if (mode == 2){
                x0 = fmaxf(x0, 0.f); x1 = fmaxf(x1, 0.f);
                __nv_bfloat16 h0,l0,h1,l1; bsplit(x0,h0,l0); bsplit(x1,h1,l1);
                *(uint32_t*)&Ch[(size_t)row*N + col] = pack2(h0,h1);
                *(uint32_t*)&Cl[(size_t)row*N + col] = pack2(l0,l1);
            } else {
                *(float2*)&Cf[(size_t)row*N + col] = make_float2(x0, x1);
            }
        }
    }
}

__global__ __launch_bounds__(512) void attn_kernel(
    const float* __restrict__ q, const float* __restrict__ k,
    const float* __restrict__ v, const unsigned char* __restrict__ mask,
    __nv_bfloat16* __restrict__ ch, __nv_bfloat16* __restrict__ cl)
{
    const int bl = blockIdx.x, b = bl>>12, l = bl&4095;
    const int wid = threadIdx.x>>5, lane = threadIdx.x&31;
    const size_t base = (size_t)bl*Dd + wid*64;
    const float q0 = q[base+lane], q1 = q[base+lane+32];
    float sc[3]; int lks[3];
#pragma unroll
    for (int w = 0; w < 3; w++){
        int lk = l + w - 1;
        bool inb = (lk >= 0) && (lk < Ll);
        int lkc = lk < 0 ? 0 : (lk > Ll-1 ? Ll-1 : lk);
        lks[w] = lkc;
        bool ok = inb && (mask[(b<<12)+lkc] == 0);
        const size_t kb = ((size_t)(b<<12)+lkc)*Dd + wid*64;
        float d = q0*k[kb+lane] + q1*k[kb+lane+32];
#pragma unroll
        for (int o = 16; o; o >>= 1) d += __shfl_xor_sync(0xffffffffu, d, o);
        sc[w] = ok ? d*0.125f : -1e30f;
    }
    float m = fmaxf(sc[0], fmaxf(sc[1], sc[2]));
    float e0 = expf(sc[0]-m), e1 = expf(sc[1]-m), e2 = expf(sc[2]-m);
    float inv = 1.f/(e0+e1+e2);
    float a0 = e0*inv, a1 = e1*inv, a2 = e2*inv;
    float c0 = 0.f, c1 = 0.f;
#pragma unroll
    for (int w = 0; w < 3; w++){
        const float aw = (w==0)?a0:(w==1?a1:a2);
        const size_t vb = ((size_t)(b<<12)+lks[w])*Dd + wid*64;
        c0 += aw*v[vb+lane]; c1 += aw*v[vb+lane+32];
    }
    __nv_bfloat16 h0,l0,h1,l1; bsplit(c0,h0,l0); bsplit(c1,h1,l1);
    ch[base+lane]=h0; cl[base+lane]=l0;
    ch[base+lane+32]=h1; cl[base+lane+32]=l1;
}

__global__ __launch_bounds__(256) void ln_kernel(
    const float* __restrict__ X, const float* __restrict__ gam,
    const float* __restrict__ bet, float* __restrict__ Y,
    __nv_bfloat16* __restrict__ Yh, __nv_bfloat16* __restrict__ Yl)
{
    const int row = blockIdx.x, tid = threadIdx.x;
    float4 vv = ((const float4*)(X + (size_t)row*Dd))[tid];
    float s = vv.x+vv.y+vv.z+vv.w;
    float ss = vv.x*vv.x+vv.y*vv.y+vv.z*vv.z+vv.w*vv.w;
#pragma unroll
    for (int o = 16; o; o >>= 1){
        s += __shfl_xor_sync(0xffffffffu, s, o);
        ss += __shfl_xor_sync(0xffffffffu, ss, o);
    }
    __shared__ float sh_s[8], sh_ss[8];
    const int w = tid>>5, lane = tid&31;
    if (lane == 0){ sh_s[w]=s; sh_ss[w]=ss; }
    __syncthreads();
    s = 0.f; ss = 0.f;
#pragma unroll
    for (int i = 0; i < 8; i++){ s += sh_s[i]; ss += sh_ss[i]; }
    const float mean = s*(1.f/Dd);
    const float var = ss*(1.f/Dd) - mean*mean;
    const float rstd = rsqrtf(var + 1e-5f);
    float4 g4 = ((const float4*)gam)[tid], b4 = ((const float4*)bet)[tid];
    float4 o;
    o.x=(vv.x-mean)*rstd*g4.x+b4.x; o.y=(vv.y-mean)*rstd*g4.y+b4.y;
    o.z=(vv.z-mean)*rstd*g4.z+b4.z; o.w=(vv.w-mean)*rstd*g4.w+b4.w;
    ((float4*)(Y + (size_t)row*Dd))[tid] = o;
    if (Yh){
        __nv_bfloat16 h0,l0,h1,l1,h2,l2,h3,l3;
        bsplit(o.x,h0,l0); bsplit(o.y,h1,l1); bsplit(o.z,h2,l2); bsplit(o.w,h3,l3);
        size_t i = (size_t)row*(Dd/4) + tid;
        ((uint32_t*)Yh)[i*2]=pack2(h0,h1); ((uint32_t*)Yh)[i*2+1]=pack2(h2,h3);
        ((uint32_t*)Yl)[i*2]=pack2(l0,l1); ((uint32_t*)Yl)[i*2+1]=pack2(l2,l3);
    }
}

extern "C" void kernel_launch(void* const* d_in, const int* in_sizes, int n_in,
                              void* d_out, int out_size)
{
    const float* X = (const float*)d_in[0];
    const unsigned char* mask = (const unsigned char*)d_in[1];
    const float* pe = (const float*)d_in[2];
    const float *Wq=(const float*)d_in[3], *Wk=(const float*)d_in[4], *Wv=(const float*)d_in[5];
    const float *bq=(const float*)d_in[6], *bk=(const float*)d_in[7], *bv=(const float*)d_in[8];
    const float *Wo=(const float*)d_in[9], *bo=(const float*)d_in[10];
    const float *g1=(const float*)d_in[11], *be1=(const float*)d_in[12];
    const float *W1=(const float*)d_in[13], *b1=(const float*)d_in[14];
    const float *W2=(const float*)d_in[15], *b2=(const float*)d_in[16];
    const float *g2=(const float*)d_in[17], *be2=(const float*)d_in[18];
    float* out = (float*)d_out;

    float *xp,*q,*k,*v,*y1,*x1;
    __nv_bfloat16 *xph,*xpl,*ch,*cl,*x1h,*x1l,*hh,*hl;
    __nv_bfloat16 *wqh,*wql,*wkh,*wkl,*wvh,*wvl,*woh,*wol,*w1h,*w1l,*w2h,*w2l;
    cudaGetSymbolAddress((void**)&xp,g_xp);   cudaGetSymbolAddress((void**)&q,g_q);
    cudaGetSymbolAddress((void**)&k,g_k);     cudaGetSymbolAddress((void**)&v,g_v);
    cudaGetSymbolAddress((void**)&y1,g_y1);   cudaGetSymbolAddress((void**)&x1,g_x1);
    cudaGetSymbolAddress((void**)&xph,g_xph); cudaGetSymbolAddress((void**)&xpl,g_xpl);
    cudaGetSymbolAddress((void**)&ch,g_ch);   cudaGetSymbolAddress((void**)&cl,g_cl);
    cudaGetSymbolAddress((void**)&x1h,g_x1h); cudaGetSymbolAddress((void**)&x1l,g_x1l);
    cudaGetSymbolAddress((void**)&hh,g_hh);   cudaGetSymbolAddress((void**)&hl,g_hl);
    cudaGetSymbolAddress((void**)&wqh,g_wqh); cudaGetSymbolAddress((void**)&wql,g_wql);
    cudaGetSymbolAddress((void**)&wkh,g_wkh); cudaGetSymbolAddress((void**)&wkl,g_wkl);
    cudaGetSymbolAddress((void**)&wvh,g_wvh); cudaGetSymbolAddress((void**)&wvl,g_wvl);
    cudaGetSymbolAddress((void**)&woh,g_woh); cudaGetSymbolAddress((void**)&wol,g_wol);
    cudaGetSymbolAddress((void**)&w1h,g_w1h); cudaGetSymbolAddress((void**)&w1l,g_w1l);
    cudaGetSymbolAddress((void**)&w2h,g_w2h); cudaGetSymbolAddress((void**)&w2l,g_w2l);

    const size_t sm = STAGES*STGB;   // 96KB
    cudaFuncSetAttribute(tgemm, cudaFuncAttributeMaxDynamicSharedMemorySize, (int)sm);

    addpe_split<<<8192,256>>>(X, pe, xp, xph, xpl);
    wtrans<<<dim3(32,32),256>>>(Wq, Dd, Dd, wqh, wql);
    wtrans<<<dim3(32,32),256>>>(Wk, Dd, Dd, wkh, wkl);
    wtrans<<<dim3(32,32),256>>>(Wv, Dd, Dd, wvh, wvl);
    wtrans<<<dim3(32,32),256>>>(Wo, Dd, Dd, woh, wol);
    wtrans<<<dim3(128,32),256>>>(W1, Dd, FFD, w1h, w1l);
    wtrans<<<dim3(32,128),256>>>(W2, FFD, Dd, w2h, w2l);

    const dim3 gDD(Dd/128, Mrows/128);   // (8, 256)
    const dim3 gDF(FFD/128, Mrows/128);  // (32, 256)

    tgemm<<<gDD,256,sm>>>(xph, xpl, wqh, wql, bq, nullptr, q, nullptr, nullptr, Dd, Dd, 0);
    tgemm<<<gDD,256,sm>>>(xph, xpl, wkh, wkl, bk, nullptr, k, nullptr, nullptr, Dd, Dd, 0);
    tgemm<<<gDD,256,sm>>>(xph, xpl, wvh, wvl, bv, nullptr, v, nullptr, nullptr, Dd, Dd, 0);

    attn_kernel<<<Mrows,512>>>(q, k, v, mask, ch, cl);

    tgemm<<<gDD,256,sm>>>(ch, cl, woh, wol, bo, xp, y1, nullptr, nullptr, Dd, Dd, 1);
    ln_kernel<<<Mrows,256>>>(y1, g1, be1, x1, x1h, x1l);

    tgemm<<<gDF,256,sm>>>(x1h, x1l, w1h, w1l, b1, nullptr, nullptr, hh, hl, Dd, FFD, 2);
    tgemm<<<gDD,256,sm>>>(hh, hl, w2h, w2l, b2, x1, y1, nullptr, nullptr, FFD, Dd, 1);
    ln_kernel<<<Mrows,256>>>(y1, g2, be2, out, nullptr, nullptr);
}

// round 7
// speedup vs baseline: 4.3832x; 1.4532x over previous
#include <cuda_runtime.h>
#include <cuda_fp16.h>
#include <cstdint>

#define Bb 8
#define Ll 4096
#define Dd 1024
#define FFD 4096
#define Mrows (Bb*Ll)
#define NE   (Mrows*Dd)
#define NEFF (Mrows*FFD)

__device__ float g_xp[NE];                 // X + pe (fp32, residual)
__device__ float g_qkv[Mrows*3072];        // fused QKV output
__device__ float g_y1[NE], g_x1[NE];
__device__ float g_bqkv[3072];
__device__ __half g_xph[NE], g_ch[NE], g_x1h[NE], g_hh[NEFF];
__device__ __half g_wqkvh[3*Dd*Dd], g_wqkvl[3*Dd*Dd];
__device__ __half g_woh[Dd*Dd], g_wol[Dd*Dd];
__device__ __half g_w1h[Dd*FFD], g_w1l[Dd*FFD];
__device__ __half g_w2h[FFD*Dd], g_w2l[FFD*Dd];

__device__ __forceinline__ uint32_t smem_u32(const void* p){
    uint32_t a; asm("{ .reg .u64 t; cvta.to.shared.u64 t, %1; cvt.u32.u64 %0, t; }":"=r"(a):"l"(p)); return a;
}
__device__ __forceinline__ void hsplit(float v, __half& h, __half& l){
    h = __float2half(v); l = __float2half(v - __half2float(h));
}
__device__ __forceinline__ uint32_t hpack2(__half a, __half b){
    return (uint32_t)__half_as_ushort(a) | ((uint32_t)__half_as_ushort(b) << 16);
}

#define LDSM4(r0,r1,r2,r3,ad) \
    asm volatile("ldmatrix.sync.aligned.m8n8.x4.shared.b16 {%0,%1,%2,%3}, [%4];" \
        : "=r"(r0),"=r"(r1),"=r"(r2),"=r"(r3) : "r"(ad))

#define MMAH(d,a0,a1,a2,a3,b0,b1) \
    asm volatile("mma.sync.aligned.m16n8k16.row.col.f32.f16.f16.f32 " \
        "{%0,%1,%2,%3},{%4,%5,%6,%7},{%8,%9},{%0,%1,%2,%3};" \
        : "+f"((d)[0]),"+f"((d)[1]),"+f"((d)[2]),"+f"((d)[3]) \
        : "r"(a0),"r"(a1),"r"(a2),"r"(a3),"r"(b0),"r"(b1))

#define CPA16(sd,gp) asm volatile("cp.async.cg.shared.global [%0], [%1], 16;"::"r"(sd),"l"(gp):"memory")

__global__ __launch_bounds__(256) void addpe_split(
    const float* __restrict__ X, const float* __restrict__ pe,
    float* __restrict__ xp, __half* __restrict__ xh)
{
    const size_t n4 = (size_t)NE/4, pe4 = (size_t)Ll*Dd/4;
    for (size_t i = (size_t)blockIdx.x*blockDim.x+threadIdx.x; i < n4; i += (size_t)gridDim.x*blockDim.x){
        float4 a = ((const float4*)X)[i]; float4 p = ((const float4*)pe)[i % pe4];
        a.x+=p.x; a.y+=p.y; a.z+=p.z; a.w+=p.w;
        ((float4*)xp)[i] = a;
        ((uint32_t*)xh)[i*2]   = hpack2(__float2half(a.x), __float2half(a.y));
        ((uint32_t*)xh)[i*2+1] = hpack2(__float2half(a.z), __float2half(a.w));
    }
}

__global__ __launch_bounds__(256) void wtrans(
    const float* __restrict__ W, int K, int N,
    __half* __restrict__ Th, __half* __restrict__ Tl)
{
    __shared__ float t[32][33];
    const int bn = blockIdx.x*32, bk = blockIdx.y*32;
    const int tx = threadIdx.x&31, ty = threadIdx.x>>5;
#pragma unroll
    for (int r = 0; r < 32; r += 8) t[ty+r][tx] = W[(size_t)(bk+ty+r)*N + bn+tx];
    __syncthreads();
#pragma unroll
    for (int r = 0; r < 32; r += 8){
        float v = t[tx][ty+r];
        __half h,l; hsplit(v,h,l);
        size_t o = (size_t)(bn+ty+r)*K + bk+tx;
        Th[o]=h; Tl[o]=l;
    }
}

__global__ __launch_bounds__(256) void catb3(
    const float* __restrict__ a, const float* __restrict__ b,
    const float* __restrict__ c, float* __restrict__ o)
{
    int i = blockIdx.x*256 + threadIdx.x;
    if (i < 1024) o[i] = a[i];
    else if (i < 2048) o[i] = b[i-1024];
    else if (i < 3072) o[i] = c[i-2048];
}

// ---- HMMA GEMM: D[M,N] = A[M,K] @ (Bh+Bl)[N,K]^T, fp16, single accumulator ----
// BM=128 BN=128 BK=64, 3 stages x 48KB, 256 thr (8 warps 2m x 4n, warp 64x32)
#define STAGES 3
#define STGB 49152

__device__ __forceinline__ void load_op(uint32_t sdst, const __half* __restrict__ g,
                                        int ldk, int row0, int k0, int tid)
{
    const __half* gb = g + (size_t)row0*ldk + k0;
#pragma unroll
    for (int t = 0; t < 4; ++t){
        int idx = t*256 + tid;
        int row = idx >> 3, j = idx & 7;
        uint32_t so = (uint32_t)row*128u + (((uint32_t)j*16u) ^ (((uint32_t)row&7u)*16u));
        CPA16(sdst + so, gb + (size_t)row*ldk + j*8);
    }
}

// mode 0: bias->Cf ; 1: bias+R->Cf ; 2: relu(bias)->Ch(fp16)
__global__ void __launch_bounds__(256) tgemm(
    const __half* __restrict__ Ah,
    const __half* __restrict__ Bh, const __half* __restrict__ Bl,
    const float* __restrict__ bias, const float* __restrict__ Rres,
    float* __restrict__ Cf, __half* __restrict__ Ch,
    int K, int N, int mode)
{
    extern __shared__ char smem[];
    const uint32_t sb = smem_u32(smem);
    const int tid = threadIdx.x, wid = tid>>5, lane = tid&31;
    const int wm = wid & 1, wn = wid >> 1;
    const int m0 = blockIdx.y*128, n0 = blockIdx.x*128;
    const int T = K >> 6;

    float acc[4][4][4];
#pragma unroll
    for (int a=0;a<4;a++)
#pragma unroll
    for (int b=0;b<4;b++)
#pragma unroll
    for (int c=0;c<4;c++) acc[a][b][c]=0.f;

#pragma unroll
    for (int it = 0; it < STAGES-1; ++it){
        const int kk = it*64;
        load_op(sb + it*STGB,          Ah, K, m0, kk, tid);
        load_op(sb + it*STGB + 16384,  Bh, K, n0, kk, tid);
        load_op(sb + it*STGB + 32768,  Bl, K, n0, kk, tid);
        asm volatile("cp.async.commit_group;":::"memory");
    }

    const int r16 = lane & 15, cg = lane >> 4;
    for (int it = 0; it < T; ++it){
        if (it == T-1) asm volatile("cp.async.wait_group 0;":::"memory");
        else           asm volatile("cp.async.wait_group %0;"::"n"(STAGES-2):"memory");
        __syncthreads();
        if (it + STAGES-1 < T){
            const int it2 = it + STAGES-1, kk = it2*64;
            const uint32_t slot = sb + (it2 % STAGES)*STGB;
            load_op(slot,         Ah, K, m0, kk, tid);
            load_op(slot + 16384, Bh, K, n0, kk, tid);
            load_op(slot + 32768, Bl, K, n0, kk, tid);
            asm volatile("cp.async.commit_group;":::"memory");
        }
        const uint32_t sA = sb + (it % STAGES)*STGB;
        const uint32_t sBh = sA + 16384u, sBl = sA + 32768u;
#pragma unroll
        for (int kk = 0; kk < 4; ++kk){
            const uint32_t col = (uint32_t)kk*32u + (uint32_t)cg*16u;
            uint32_t a[4][4], bh[2][4], bl[2][4];
#pragma unroll
            for (int mi = 0; mi < 4; ++mi){
                int row = wm*64 + mi*16 + r16;
                uint32_t ad = sA + (uint32_t)row*128u + (col ^ (((uint32_t)row&7u)*16u));
                LDSM4(a[mi][0],a[mi][1],a[mi][2],a[mi][3], ad);
            }
#pragma unroll
            for (int nb = 0; nb < 2; ++nb){
                int row = wn*32 + nb*16 + r16;
                uint32_t off = (uint32_t)row*128u + (col ^ (((uint32_t)row&7u)*16u));
                LDSM4(bh[nb][0],bh[nb][1],bh[nb][2],bh[nb][3], sBh + off);
                LDSM4(bl[nb][0],bl[nb][1],bl[nb][2],bl[nb][3], sBl + off);
            }
#pragma unroll
            for (int mi = 0; mi < 4; ++mi)
#pragma unroll
                for (int nj = 0; nj < 4; ++nj){
                    const int nb = nj>>1, hf = nj&1;
                    MMAH(acc[mi][nj], a[mi][0],a[mi][1],a[mi][2],a[mi][3],
                         bh[nb][hf], bh[nb][hf+2]);
                    MMAH(acc[mi][nj], a[mi][0],a[mi][1],a[mi][2],a[mi][3],
                         bl[nb][hf], bl[nb][hf+2]);
                }
        }
        __syncthreads();
    }

    const int mwb = m0 + wm*64, nwb = n0 + wn*32;
#pragma unroll
    for (int mi = 0; mi < 4; ++mi)
#pragma unroll
    for (int nj = 0; nj < 4; ++nj){
        const int col = nwb + nj*8 + (lane&3)*2;
        const float2 bb = *(const float2*)&bias[col];
#pragma unroll
        for (int h = 0; h < 2; ++h){
            const int row = mwb + mi*16 + (lane>>2) + h*8;
            float x0 = acc[mi][nj][h*2+0] + bb.x;
            float x1 = acc[mi][nj][h*2+1] + bb.y;
            if (mode == 1){
                float2 rr = *(const float2*)&Rres[(size_t)row*N + col];
                x0 += rr.x; x1 += rr.y;
            }
            if (mode == 2){
                x0 = fmaxf(x0, 0.f); x1 = fmaxf(x1, 0.f);
                *(uint32_t*)&Ch[(size_t)row*N + col] = hpack2(__float2half(x0), __float2half(x1));
            } else {
                *(float2*)&Cf[(size_t)row*N + col] = make_float2(x0, x1);
            }
        }
    }
}

// ---- window-3 attention on fused qkv [M,3072]; fp16 ctx out ----
__global__ __launch_bounds__(512) void attn_kernel(
    const float* __restrict__ qkv, const unsigned char* __restrict__ mask,
    __half* __restrict__ ch)
{
    const int bl = blockIdx.x, b = bl>>12, l = bl&4095;
    const int wid = threadIdx.x>>5, lane = threadIdx.x&31;
    const size_t qb = (size_t)bl*3072 + wid*64;
    const float q0 = qkv[qb+lane], q1 = qkv[qb+lane+32];
    float sc[3]; int lks[3];
#pragma unroll
    for (int w = 0; w < 3; w++){
        int lk = l + w - 1;
        bool inb = (lk >= 0) && (lk < Ll);
        int lkc = lk < 0 ? 0 : (lk > Ll-1 ? Ll-1 : lk);
        lks[w] = lkc;
        bool ok = inb && (mask[(b<<12)+lkc] == 0);
        const size_t kb = (size_t)((b<<12)+lkc)*3072 + 1024 + wid*64;
        float d = q0*qkv[kb+lane] + q1*qkv[kb+lane+32];
#pragma unroll
        for (int o = 16; o; o >>= 1) d += __shfl_xor_sync(0xffffffffu, d, o);
        sc[w] = ok ? d*0.125f : -1e30f;
    }
    float m = fmaxf(sc[0], fmaxf(sc[1], sc[2]));
    float e0 = expf(sc[0]-m), e1 = expf(sc[1]-m), e2 = expf(sc[2]-m);
    float inv = 1.f/(e0+e1+e2);
    float a0 = e0*inv, a1 = e1*inv, a2 = e2*inv;
    float c0 = 0.f, c1 = 0.f;
#pragma unroll
    for (int w = 0; w < 3; w++){
        const float aw = (w==0)?a0:(w==1?a1:a2);
        const size_t vb = (size_t)((b<<12)+lks[w])*3072 + 2048 + wid*64;
        c0 += aw*qkv[vb+lane]; c1 += aw*qkv[vb+lane+32];
    }
    const size_t ob = (size_t)bl*Dd + wid*64;
    ch[ob+lane]    = __float2half(c0);
    ch[ob+lane+32] = __float2half(c1);
}

__global__ __launch_bounds__(256) void ln_kernel(
    const float* __restrict__ X, const float* __restrict__ gam,
    const float* __restrict__ bet, float* __restrict__ Y, __half* __restrict__ Yh)
{
    const int row = blockIdx.x, tid = threadIdx.x;
    float4 vv = ((const float4*)(X + (size_t)row*Dd))[tid];
    float s = vv.x+vv.y+vv.z+vv.w;
    float ss = vv.x*vv.x+vv.y*vv.y+vv.z*vv.z+vv.w*vv.w;
#pragma unroll
    for (int o = 16; o; o >>= 1){
        s += __shfl_xor_sync(0xffffffffu, s, o);
        ss += __shfl_xor_sync(0xffffffffu, ss, o);
    }
    __shared__ float sh_s[8], sh_ss[8];
    const int w = tid>>5, lane = tid&31;
    if (lane == 0){ sh_s[w]=s; sh_ss[w]=ss; }
    __syncthreads();
    s = 0.f; ss = 0.f;
#pragma unroll
    for (int i = 0; i < 8; i++){ s += sh_s[i]; ss += sh_ss[i]; }
    const float mean = s*(1.f/Dd);
    const float var = ss*(1.f/Dd) - mean*mean;
    const float rstd = rsqrtf(var + 1e-5f);
    float4 g4 = ((const float4*)gam)[tid], b4 = ((const float4*)bet)[tid];
    float4 o;
    o.x=(vv.x-mean)*rstd*g4.x+b4.x; o.y=(vv.y-mean)*rstd*g4.y+b4.y;
    o.z=(vv.z-mean)*rstd*g4.z+b4.z; o.w=(vv.w-mean)*rstd*g4.w+b4.w;
    ((float4*)(Y + (size_t)row*Dd))[tid] = o;
    if (Yh){
        size_t i = (size_t)row*(Dd/4) + tid;
        ((uint32_t*)Yh)[i*2]   = hpack2(__float2half(o.x), __float2half(o.y));
        ((uint32_t*)Yh)[i*2+1] = hpack2(__float2half(o.z), __float2half(o.w));
    }
}

extern "C" void kernel_launch(void* const* d_in, const int* in_sizes, int n_in,
                              void* d_out, int out_size)
{
    const float* X = (const float*)d_in[0];
    const unsigned char* mask = (const unsigned char*)d_in[1];
    const float* pe = (const float*)d_in[2];
    const float *Wq=(const float*)d_in[3], *Wk=(const float*)d_in[4], *Wv=(const float*)d_in[5];
    const float *bq=(const float*)d_in[6], *bk=(const float*)d_in[7], *bv=(const float*)d_in[8];
    const float *Wo=(const float*)d_in[9], *bo=(const float*)d_in[10];
    const float *g1=(const float*)d_in[11], *be1=(const float*)d_in[12];
    const float *W1=(const float*)d_in[13], *b1=(const float*)d_in[14];
    const float *W2=(const float*)d_in[15], *b2=(const float*)d_in[16];
    const float *g2=(const float*)d_in[17], *be2=(const float*)d_in[18];
    float* out = (float*)d_out;

    float *xp,*qkv,*y1,*x1,*bqkv;
    __half *xph,*ch,*x1h,*hh;
    __half *wqkvh,*wqkvl,*woh,*wol,*w1h,*w1l,*w2h,*w2l;
    cudaGetSymbolAddress((void**)&xp,g_xp);     cudaGetSymbolAddress((void**)&qkv,g_qkv);
    cudaGetSymbolAddress((void**)&y1,g_y1);     cudaGetSymbolAddress((void**)&x1,g_x1);
    cudaGetSymbolAddress((void**)&bqkv,g_bqkv);
    cudaGetSymbolAddress((void**)&xph,g_xph);   cudaGetSymbolAddress((void**)&ch,g_ch);
    cudaGetSymbolAddress((void**)&x1h,g_x1h);   cudaGetSymbolAddress((void**)&hh,g_hh);
    cudaGetSymbolAddress((void**)&wqkvh,g_wqkvh); cudaGetSymbolAddress((void**)&wqkvl,g_wqkvl);
    cudaGetSymbolAddress((void**)&woh,g_woh);   cudaGetSymbolAddress((void**)&wol,g_wol);
    cudaGetSymbolAddress((void**)&w1h,g_w1h);   cudaGetSymbolAddress((void**)&w1l,g_w1l);
    cudaGetSymbolAddress((void**)&w2h,g_w2h);   cudaGetSymbolAddress((void**)&w2l,g_w2l);

    const size_t sm = STAGES*STGB;   // 144KB
    cudaFuncSetAttribute(tgemm, cudaFuncAttributeMaxDynamicSharedMemorySize, (int)sm);

    addpe_split<<<8192,256>>>(X, pe, xp, xph);
    // fused QKV weight: rows 0-1023 = Wq^T, 1024-2047 = Wk^T, 2048-3071 = Wv^T
    wtrans<<<dim3(32,32),256>>>(Wq, Dd, Dd, wqkvh,              wqkvl);
    wtrans<<<dim3(32,32),256>>>(Wk, Dd, Dd, wqkvh + 1024*1024,  wqkvl + 1024*1024);
    wtrans<<<dim3(32,32),256>>>(Wv, Dd, Dd, wqkvh + 2048*1024,  wqkvl + 2048*1024);
    wtrans<<<dim3(32,32),256>>>(Wo, Dd, Dd, woh, wol);
    wtrans<<<dim3(128,32),256>>>(W1, Dd, FFD, w1h, w1l);
    wtrans<<<dim3(32,128),256>>>(W2, FFD, Dd, w2h, w2l);
    catb3<<<12,256>>>(bq, bk, bv, bqkv);

    const dim3 gQKV(3072/128, Mrows/128);  // (24, 256)
    const dim3 gDD(Dd/128, Mrows/128);     // (8, 256)
    const dim3 gDF(FFD/128, Mrows/128);    // (32, 256)

    tgemm<<<gQKV,256,sm>>>(xph, wqkvh, wqkvl, bqkv, nullptr, qkv, nullptr, Dd, 3072, 0);

    attn_kernel<<<Mrows,512>>>(qkv, mask, ch);

    tgemm<<<gDD,256,sm>>>(ch, woh, wol, bo, xp, y1, nullptr, Dd, Dd, 1);
    ln_kernel<<<Mrows,256>>>(y1, g1, be1, x1, x1h);

    tgemm<<<gDF,256,sm>>>(x1h, w1h, w1l, b1, nullptr, nullptr, hh, Dd, FFD, 2);
    tgemm<<<gDD,256,sm>>>(hh, w2h, w2l, b2, x1, y1, nullptr, FFD, Dd, 1);
    ln_kernel<<<Mrows,256>>>(y1, g2, be2, out, nullptr);
}

// round 8
// speedup vs baseline: 8.0212x; 1.8300x over previous
#include <cuda_runtime.h>
#include <cuda_fp16.h>
#include <cstdint>

#define Bb 8
#define Ll 4096
#define Dd 1024
#define FFD 4096
#define Mrows (Bb*Ll)
#define NE   (Mrows*Dd)
#define NEFF (Mrows*FFD)

__device__ float g_xp[NE];                 // X + pe (fp32, residual)
__device__ float g_qkv[Mrows*3072];        // fused QKV output
__device__ float g_y1[NE], g_x1[NE];
__device__ float g_bqkv[3072];
__device__ __half g_xph[NE], g_ch[NE], g_x1h[NE], g_hh[NEFF];
__device__ __half g_wqkvh[3*Dd*Dd];
__device__ __half g_woh[Dd*Dd];
__device__ __half g_w1h[Dd*FFD];
__device__ __half g_w2h[FFD*Dd];

__device__ __forceinline__ uint32_t smem_u32(const void* p){
    uint32_t a; asm("{ .reg .u64 t; cvta.to.shared.u64 t, %1; cvt.u32.u64 %0, t; }":"=r"(a):"l"(p)); return a;
}
__device__ __forceinline__ uint32_t hpack2(__half a, __half b){
    return (uint32_t)__half_as_ushort(a) | ((uint32_t)__half_as_ushort(b) << 16);
}

#define LDSM4(r0,r1,r2,r3,ad) \
    asm volatile("ldmatrix.sync.aligned.m8n8.x4.shared.b16 {%0,%1,%2,%3}, [%4];" \
        : "=r"(r0),"=r"(r1),"=r"(r2),"=r"(r3) : "r"(ad))

#define MMAH(d,a0,a1,a2,a3,b0,b1) \
    asm volatile("mma.sync.aligned.m16n8k16.row.col.f32.f16.f16.f32 " \
        "{%0,%1,%2,%3},{%4,%5,%6,%7},{%8,%9},{%0,%1,%2,%3};" \
        : "+f"((d)[0]),"+f"((d)[1]),"+f"((d)[2]),"+f"((d)[3]) \
        : "r"(a0),"r"(a1),"r"(a2),"r"(a3),"r"(b0),"r"(b1))

#define CPA16(sd,gp) asm volatile("cp.async.cg.shared.global [%0], [%1], 16;"::"r"(sd),"l"(gp):"memory")

__global__ __launch_bounds__(256) void addpe_split(
    const float* __restrict__ X, const float* __restrict__ pe,
    float* __restrict__ xp, __half* __restrict__ xh)
{
    const size_t n4 = (size_t)NE/4, pe4 = (size_t)Ll*Dd/4;
    for (size_t i = (size_t)blockIdx.x*blockDim.x+threadIdx.x; i < n4; i += (size_t)gridDim.x*blockDim.x){
        float4 a = ((const float4*)X)[i]; float4 p = ((const float4*)pe)[i % pe4];
        a.x+=p.x; a.y+=p.y; a.z+=p.z; a.w+=p.w;
        ((float4*)xp)[i] = a;
        ((uint32_t*)xh)[i*2]   = hpack2(__float2half(a.x), __float2half(a.y));
        ((uint32_t*)xh)[i*2+1] = hpack2(__float2half(a.z), __float2half(a.w));
    }
}

__global__ __launch_bounds__(256) void wtrans(
    const float* __restrict__ W, int K, int N, __half* __restrict__ Th)
{
    __shared__ float t[32][33];
    const int bn = blockIdx.x*32, bk = blockIdx.y*32;
    const int tx = threadIdx.x&31, ty = threadIdx.x>>5;
#pragma unroll
    for (int r = 0; r < 32; r += 8) t[ty+r][tx] = W[(size_t)(bk+ty+r)*N + bn+tx];
    __syncthreads();
#pragma unroll
    for (int r = 0; r < 32; r += 8){
        Th[(size_t)(bn+ty+r)*K + bk+tx] = __float2half(t[tx][ty+r]);
    }
}

__global__ __launch_bounds__(256) void catb3(
    const float* __restrict__ a, const float* __restrict__ b,
    const float* __restrict__ c, float* __restrict__ o)
{
    int i = blockIdx.x*256 + threadIdx.x;
    if (i < 1024) o[i] = a[i];
    else if (i < 2048) o[i] = b[i-1024];
    else if (i < 3072) o[i] = c[i-2048];
}

// ---- HMMA GEMM: D[M,N] = A[M,K] @ B[N,K]^T, pure fp16, fp32 accum ----
// BM=128 BN=128 BK=64, 3 stages x 32KB (96KB -> 2 CTAs/SM), 256 thr
// 8 warps 2m x 4n, warp tile 64x32
#define STAGES 3
#define STGB 32768

__device__ __forceinline__ void load_op(uint32_t sdst, const __half* __restrict__ g,
                                        int ldk, int row0, int k0, int tid)
{
    const __half* gb = g + (size_t)row0*ldk + k0;
#pragma unroll
    for (int t = 0; t < 4; ++t){
        int idx = t*256 + tid;
        int row = idx >> 3, j = idx & 7;
        uint32_t so = (uint32_t)row*128u + (((uint32_t)j*16u) ^ (((uint32_t)row&7u)*16u));
        CPA16(sdst + so, gb + (size_t)row*ldk + j*8);
    }
}

// mode 0: bias->Cf ; 1: bias+R->Cf ; 2: relu(bias)->Ch(fp16)
__global__ void __launch_bounds__(256) tgemm(
    const __half* __restrict__ Ah, const __half* __restrict__ Bh,
    const float* __restrict__ bias, const float* __restrict__ Rres,
    float* __restrict__ Cf, __half* __restrict__ Ch,
    int K, int N, int mode)
{
    extern __shared__ char smem[];
    const uint32_t sb = smem_u32(smem);
    const int tid = threadIdx.x, wid = tid>>5, lane = tid&31;
    const int wm = wid & 1, wn = wid >> 1;
    const int m0 = blockIdx.y*128, n0 = blockIdx.x*128;
    const int T = K >> 6;

    float acc[4][4][4];
#pragma unroll
    for (int a=0;a<4;a++)
#pragma unroll
    for (int b=0;b<4;b++)
#pragma unroll
    for (int c=0;c<4;c++) acc[a][b][c]=0.f;

#pragma unroll
    for (int it = 0; it < STAGES-1; ++it){
        const int kk = it*64;
        load_op(sb + it*STGB,          Ah, K, m0, kk, tid);
        load_op(sb + it*STGB + 16384,  Bh, K, n0, kk, tid);
        asm volatile("cp.async.commit_group;":::"memory");
    }

    const int r16 = lane & 15, cg = lane >> 4;
    for (int it = 0; it < T; ++it){
        if (it == T-1) asm volatile("cp.async.wait_group 0;":::"memory");
        else           asm volatile("cp.async.wait_group %0;"::"n"(STAGES-2):"memory");
        __syncthreads();
        if (it + STAGES-1 < T){
            const int it2 = it + STAGES-1, kk = it2*64;
            const uint32_t slot = sb + (it2 % STAGES)*STGB;
            load_op(slot,         Ah, K, m0, kk, tid);
            load_op(slot + 16384, Bh, K, n0, kk, tid);
            asm volatile("cp.async.commit_group;":::"memory");
        }
        const uint32_t sA = sb + (it % STAGES)*STGB, sB = sA + 16384u;
#pragma unroll
        for (int kk = 0; kk < 4; ++kk){
            const uint32_t col = (uint32_t)kk*32u + (uint32_t)cg*16u;
            uint32_t a[4][4], bfr[2][4];
#pragma unroll
            for (int mi = 0; mi < 4; ++mi){
                int row = wm*64 + mi*16 + r16;
                uint32_t ad = sA + (uint32_t)row*128u + (col ^ (((uint32_t)row&7u)*16u));
                LDSM4(a[mi][0],a[mi][1],a[mi][2],a[mi][3], ad);
            }
#pragma unroll
            for (int nb = 0; nb < 2; ++nb){
                int row = wn*32 + nb*16 + r16;
                uint32_t ad = sB + (uint32_t)row*128u + (col ^ (((uint32_t)row&7u)*16u));
                LDSM4(bfr[nb][0],bfr[nb][1],bfr[nb][2],bfr[nb][3], ad);
            }
#pragma unroll
            for (int mi = 0; mi < 4; ++mi)
#pragma unroll
                for (int nj = 0; nj < 4; ++nj){
                    const int nb = nj>>1, hf = nj&1;
                    MMAH(acc[mi][nj], a[mi][0],a[mi][1],a[mi][2],a[mi][3],
                         bfr[nb][hf], bfr[nb][hf+2]);
                }
        }
        __syncthreads();
    }

    const int mwb = m0 + wm*64, nwb = n0 + wn*32;
#pragma unroll
    for (int mi = 0; mi < 4; ++mi)
#pragma unroll
    for (int nj = 0; nj < 4; ++nj){
        const int col = nwb + nj*8 + (lane&3)*2;
        const float2 bb = *(const float2*)&bias[col];
#pragma unroll
        for (int h = 0; h < 2; ++h){
            const int row = mwb + mi*16 + (lane>>2) + h*8;
            float x0 = acc[mi][nj][h*2+0] + bb.x;
            float x1 = acc[mi][nj][h*2+1] + bb.y;
            if (mode == 1){
                float2 rr = *(const float2*)&Rres[(size_t)row*N + col];
                x0 += rr.x; x1 += rr.y;
            }
            if (mode == 2){
                x0 = fmaxf(x0, 0.f); x1 = fmaxf(x1, 0.f);
                *(uint32_t*)&Ch[(size_t)row*N + col] = hpack2(__float2half(x0), __float2half(x1));
            } else {
                *(float2*)&Cf[(size_t)row*N + col] = make_float2(x0, x1);
            }
        }
    }
}

// ---- window-3 attention on fused qkv [M,3072]; fp16 ctx out ----
__global__ __launch_bounds__(512) void attn_kernel(
    const float* __restrict__ qkv, const unsigned char* __restrict__ mask,
    __half* __restrict__ ch)
{
    const int bl = blockIdx.x, b = bl>>12, l = bl&4095;
    const int wid = threadIdx.x>>5, lane = threadIdx.x&31;
    const size_t qb = (size_t)bl*3072 + wid*64;
    const float q0 = qkv[qb+lane], q1 = qkv[qb+lane+32];
    float sc[3]; int lks[3];
#pragma unroll
    for (int w = 0; w < 3; w++){
        int lk = l + w - 1;
        bool inb = (lk >= 0) && (lk < Ll);
        int lkc = lk < 0 ? 0 : (lk > Ll-1 ? Ll-1 : lk);
        lks[w] = lkc;
        bool ok = inb && (mask[(b<<12)+lkc] == 0);
        const size_t kb = (size_t)((b<<12)+lkc)*3072 + 1024 + wid*64;
        float d = q0*qkv[kb+lane] + q1*qkv[kb+lane+32];
#pragma unroll
        for (int o = 16; o; o >>= 1) d += __shfl_xor_sync(0xffffffffu, d, o);
        sc[w] = ok ? d*0.125f : -1e30f;
    }
    float m = fmaxf(sc[0], fmaxf(sc[1], sc[2]));
    float e0 = expf(sc[0]-m), e1 = expf(sc[1]-m), e2 = expf(sc[2]-m);
    float inv = 1.f/(e0+e1+e2);
    float a0 = e0*inv, a1 = e1*inv, a2 = e2*inv;
    float c0 = 0.f, c1 = 0.f;
#pragma unroll
    for (int w = 0; w < 3; w++){
        const float aw = (w==0)?a0:(w==1?a1:a2);
        const size_t vb = (size_t)((b<<12)+lks[w])*3072 + 2048 + wid*64;
        c0 += aw*qkv[vb+lane]; c1 += aw*qkv[vb+lane+32];
    }
    const size_t ob = (size_t)bl*Dd + wid*64;
    ch[ob+lane]    = __float2half(c0);
    ch[ob+lane+32] = __float2half(c1);
}

__global__ __launch_bounds__(256) void ln_kernel(
    const float* __restrict__ X, const float* __restrict__ gam,
    const float* __restrict__ bet, float* __restrict__ Y, __half* __restrict__ Yh)
{
    const int row = blockIdx.x, tid = threadIdx.x;
    float4 vv = ((const float4*)(X + (size_t)row*Dd))[tid];
    float s = vv.x+vv.y+vv.z+vv.w;
    float ss = vv.x*vv.x+vv.y*vv.y+vv.z*vv.z+vv.w*vv.w;
#pragma unroll
    for (int o = 16; o; o >>= 1){
        s += __shfl_xor_sync(0xffffffffu, s, o);
        ss += __shfl_xor_sync(0xffffffffu, ss, o);
    }
    __shared__ float sh_s[8], sh_ss[8];
    const int w = tid>>5, lane = tid&31;
    if (lane == 0){ sh_s[w]=s; sh_ss[w]=ss; }
    __syncthreads();
    s = 0.f; ss = 0.f;
#pragma unroll
    for (int i = 0; i < 8; i++){ s += sh_s[i]; ss += sh_ss[i]; }
    const float mean = s*(1.f/Dd);
    const float var = ss*(1.f/Dd) - mean*mean;
    const float rstd = rsqrtf(var + 1e-5f);
    float4 g4 = ((const float4*)gam)[tid], b4 = ((const float4*)bet)[tid];
    float4 o;
    o.x=(vv.x-mean)*rstd*g4.x+b4.x; o.y=(vv.y-mean)*rstd*g4.y+b4.y;
    o.z=(vv.z-mean)*rstd*g4.z+b4.z; o.w=(vv.w-mean)*rstd*g4.w+b4.w;
    ((float4*)(Y + (size_t)row*Dd))[tid] = o;
    if (Yh){
        size_t i = (size_t)row*(Dd/4) + tid;
        ((uint32_t*)Yh)[i*2]   = hpack2(__float2half(o.x), __float2half(o.y));
        ((uint32_t*)Yh)[i*2+1] = hpack2(__float2half(o.z), __float2half(o.w));
    }
}

extern "C" void kernel_launch(void* const* d_in, const int* in_sizes, int n_in,
                              void* d_out, int out_size)
{
    const float* X = (const float*)d_in[0];
    const unsigned char* mask = (const unsigned char*)d_in[1];
    const float* pe = (const float*)d_in[2];
    const float *Wq=(const float*)d_in[3], *Wk=(const float*)d_in[4], *Wv=(const float*)d_in[5];
    const float *bq=(const float*)d_in[6], *bk=(const float*)d_in[7], *bv=(const float*)d_in[8];
    const float *Wo=(const float*)d_in[9], *bo=(const float*)d_in[10];
    const float *g1=(const float*)d_in[11], *be1=(const float*)d_in[12];
    const float *W1=(const float*)d_in[13], *b1=(const float*)d_in[14];
    const float *W2=(const float*)d_in[15], *b2=(const float*)d_in[16];
    const float *g2=(const float*)d_in[17], *be2=(const float*)d_in[18];
    float* out = (float*)d_out;

    float *xp,*qkv,*y1,*x1,*bqkv;
    __half *xph,*ch,*x1h,*hh;
    __half *wqkvh,*woh,*w1h,*w2h;
    cudaGetSymbolAddress((void**)&xp,g_xp);     cudaGetSymbolAddress((void**)&qkv,g_qkv);
    cudaGetSymbolAddress((void**)&y1,g_y1);     cudaGetSymbolAddress((void**)&x1,g_x1);
    cudaGetSymbolAddress((void**)&bqkv,g_bqkv);
    cudaGetSymbolAddress((void**)&xph,g_xph);   cudaGetSymbolAddress((void**)&ch,g_ch);
    cudaGetSymbolAddress((void**)&x1h,g_x1h);   cudaGetSymbolAddress((void**)&hh,g_hh);
    cudaGetSymbolAddress((void**)&wqkvh,g_wqkvh);
    cudaGetSymbolAddress((void**)&woh,g_woh);
    cudaGetSymbolAddress((void**)&w1h,g_w1h);
    cudaGetSymbolAddress((void**)&w2h,g_w2h);

    const size_t sm = STAGES*STGB;   // 96KB
    cudaFuncSetAttribute(tgemm, cudaFuncAttributeMaxDynamicSharedMemorySize, (int)sm);

    addpe_split<<<8192,256>>>(X, pe, xp, xph);
    // fused QKV weight: rows 0-1023 = Wq^T, 1024-2047 = Wk^T, 2048-3071 = Wv^T
    wtrans<<<dim3(32,32),256>>>(Wq, Dd, Dd, wqkvh);
    wtrans<<<dim3(32,32),256>>>(Wk, Dd, Dd, wqkvh + 1024*1024);
    wtrans<<<dim3(32,32),256>>>(Wv, Dd, Dd, wqkvh + 2048*1024);
    wtrans<<<dim3(32,32),256>>>(Wo, Dd, Dd, woh);
    wtrans<<<dim3(128,32),256>>>(W1, Dd, FFD, w1h);
    wtrans<<<dim3(32,128),256>>>(W2, FFD, Dd, w2h);
    catb3<<<12,256>>>(bq, bk, bv, bqkv);

    const dim3 gQKV(3072/128, Mrows/128);  // (24, 256)
    const dim3 gDD(Dd/128, Mrows/128);     // (8, 256)
    const dim3 gDF(FFD/128, Mrows/128);    // (32, 256)

    tgemm<<<gQKV,256,sm>>>(xph, wqkvh, bqkv, nullptr, qkv, nullptr, Dd, 3072, 0);

    attn_kernel<<<Mrows,512>>>(qkv, mask, ch);

    tgemm<<<gDD,256,sm>>>(ch, woh, bo, xp, y1, nullptr, Dd, Dd, 1);
    ln_kernel<<<Mrows,256>>>(y1, g1, be1, x1, x1h);

    tgemm<<<gDF,256,sm>>>(x1h, w1h, b1, nullptr, nullptr, hh, Dd, FFD, 2);
    tgemm<<<gDD,256,sm>>>(hh, w2h, b2, x1, y1, nullptr, FFD, Dd, 1);
    ln_kernel<<<Mrows,256>>>(y1, g2, be2, out, nullptr);
}

// round 9
// speedup vs baseline: 8.1391x; 1.0147x over previous
#include <cuda_runtime.h>
#include <cuda_fp16.h>
#include <cstdint>

#define Bb 8
#define Ll 4096
#define Dd 1024
#define FFD 4096
#define Mrows (Bb*Ll)
#define NE   (Mrows*Dd)
#define NEFF (Mrows*FFD)

__device__ float g_xp[NE];                 // X + pe (fp32, residual)
__device__ float g_qkv[Mrows*3072];        // fused QKV output
__device__ float g_y1[NE], g_x1[NE];
__device__ float g_bqkv[3072];
__device__ __half g_xph[NE], g_ch[NE], g_x1h[NE], g_hh[NEFF];
__device__ __half g_wqkvh[3*Dd*Dd];
__device__ __half g_woh[Dd*Dd];
__device__ __half g_w1h[Dd*FFD];
__device__ __half g_w2h[FFD*Dd];

__device__ __forceinline__ uint32_t smem_u32(const void* p){
    uint32_t a; asm("{ .reg .u64 t; cvta.to.shared.u64 t, %1; cvt.u32.u64 %0, t; }":"=r"(a):"l"(p)); return a;
}
__device__ __forceinline__ uint32_t hpack2(__half a, __half b){
    return (uint32_t)__half_as_ushort(a) | ((uint32_t)__half_as_ushort(b) << 16);
}

#define LDSM4(r0,r1,r2,r3,ad) \
    asm volatile("ldmatrix.sync.aligned.m8n8.x4.shared.b16 {%0,%1,%2,%3}, [%4];" \
        : "=r"(r0),"=r"(r1),"=r"(r2),"=r"(r3) : "r"(ad))

#define MMAH(d,a0,a1,a2,a3,b0,b1) \
    asm volatile("mma.sync.aligned.m16n8k16.row.col.f32.f16.f16.f32 " \
        "{%0,%1,%2,%3},{%4,%5,%6,%7},{%8,%9},{%0,%1,%2,%3};" \
        : "+f"((d)[0]),"+f"((d)[1]),"+f"((d)[2]),"+f"((d)[3]) \
        : "r"(a0),"r"(a1),"r"(a2),"r"(a3),"r"(b0),"r"(b1))

#define CPA16(sd,gp) asm volatile("cp.async.cg.shared.global [%0], [%1], 16;"::"r"(sd),"l"(gp):"memory")

__global__ __launch_bounds__(256) void addpe_split(
    const float* __restrict__ X, const float* __restrict__ pe,
    float* __restrict__ xp, __half* __restrict__ xh)
{
    const size_t n4 = (size_t)NE/4, pe4 = (size_t)Ll*Dd/4;
    for (size_t i = (size_t)blockIdx.x*blockDim.x+threadIdx.x; i < n4; i += (size_t)gridDim.x*blockDim.x){
        float4 a = ((const float4*)X)[i]; float4 p = ((const float4*)pe)[i % pe4];
        a.x+=p.x; a.y+=p.y; a.z+=p.z; a.w+=p.w;
        ((float4*)xp)[i] = a;
        ((uint32_t*)xh)[i*2]   = hpack2(__float2half(a.x), __float2half(a.y));
        ((uint32_t*)xh)[i*2+1] = hpack2(__float2half(a.z), __float2half(a.w));
    }
}

__global__ __launch_bounds__(256) void wtrans(
    const float* __restrict__ W, int K, int N, __half* __restrict__ Th)
{
    __shared__ float t[32][33];
    const int bn = blockIdx.x*32, bk = blockIdx.y*32;
    const int tx = threadIdx.x&31, ty = threadIdx.x>>5;
#pragma unroll
    for (int r = 0; r < 32; r += 8) t[ty+r][tx] = W[(size_t)(bk+ty+r)*N + bn+tx];
    __syncthreads();
#pragma unroll
    for (int r = 0; r < 32; r += 8){
        Th[(size_t)(bn+ty+r)*K + bk+tx] = __float2half(t[tx][ty+r]);
    }
}

__global__ __launch_bounds__(256) void catb3(
    const float* __restrict__ a, const float* __restrict__ b,
    const float* __restrict__ c, float* __restrict__ o)
{
    int i = blockIdx.x*256 + threadIdx.x;
    if (i < 1024) o[i] = a[i];
    else if (i < 2048) o[i] = b[i-1024];
    else if (i < 3072) o[i] = c[i-2048];
}

// ---- HMMA GEMM: D[M,N] = A[M,K] @ B[N,K]^T, fp16, fp32 accum ----
// BM=128 BN=128 BK=64, 4 warps (2x2), warp tile 64x64,
// 3 stages x 32KB = 96KB -> 2 CTAs/SM
#define STAGES 3
#define STGB 32768

__device__ __forceinline__ void load_op(uint32_t sdst, const __half* __restrict__ g,
                                        int ldk, int row0, int k0, int tid)
{
    const __half* gb = g + (size_t)row0*ldk + k0;
#pragma unroll
    for (int t = 0; t < 8; ++t){
        int idx = t*128 + tid;
        int row = idx >> 3, j = idx & 7;
        uint32_t so = (uint32_t)row*128u + (((uint32_t)j*16u) ^ (((uint32_t)row&7u)*16u));
        CPA16(sdst + so, gb + (size_t)row*ldk + j*8);
    }
}

// mode 0: bias->Cf ; 1: bias+R->Cf ; 2: relu(bias)->Ch(fp16)
__global__ void __launch_bounds__(128,2) tgemm(
    const __half* __restrict__ Ah, const __half* __restrict__ Bh,
    const float* __restrict__ bias, const float* __restrict__ Rres,
    float* __restrict__ Cf, __half* __restrict__ Ch,
    int K, int N, int mode)
{
    extern __shared__ char smem[];
    const uint32_t sb = smem_u32(smem);
    const int tid = threadIdx.x, wid = tid>>5, lane = tid&31;
    const int wm = wid & 1, wn = wid >> 1;     // 2x2 warps, 64x64 tiles
    const int m0 = blockIdx.y*128, n0 = blockIdx.x*128;
    const int T = K >> 6;

    float acc[4][8][4];
#pragma unroll
    for (int a=0;a<4;a++)
#pragma unroll
    for (int b=0;b<8;b++)
#pragma unroll
    for (int c=0;c<4;c++) acc[a][b][c]=0.f;

#pragma unroll
    for (int it = 0; it < STAGES-1; ++it){
        const int kk = it*64;
        load_op(sb + it*STGB,          Ah, K, m0, kk, tid);
        load_op(sb + it*STGB + 16384,  Bh, K, n0, kk, tid);
        asm volatile("cp.async.commit_group;":::"memory");
    }

    const int r16 = lane & 15, cg = lane >> 4;
    for (int it = 0; it < T; ++it){
        if (it == T-1) asm volatile("cp.async.wait_group 0;":::"memory");
        else           asm volatile("cp.async.wait_group %0;"::"n"(STAGES-2):"memory");
        __syncthreads();
        if (it + STAGES-1 < T){
            const int it2 = it + STAGES-1, kk = it2*64;
            const uint32_t slot = sb + (it2 % STAGES)*STGB;
            load_op(slot,         Ah, K, m0, kk, tid);
            load_op(slot + 16384, Bh, K, n0, kk, tid);
            asm volatile("cp.async.commit_group;":::"memory");
        }
        const uint32_t sA = sb + (it % STAGES)*STGB, sB = sA + 16384u;
#pragma unroll
        for (int kk = 0; kk < 4; ++kk){
            const uint32_t col = (uint32_t)kk*32u + (uint32_t)cg*16u;
            uint32_t a[4][4], bfr[4][4];
#pragma unroll
            for (int mi = 0; mi < 4; ++mi){
                int row = wm*64 + mi*16 + r16;
                uint32_t ad = sA + (uint32_t)row*128u + (col ^ (((uint32_t)row&7u)*16u));
                LDSM4(a[mi][0],a[mi][1],a[mi][2],a[mi][3], ad);
            }
#pragma unroll
            for (int g = 0; g < 4; ++g){
                int row = wn*64 + g*16 + r16;
                uint32_t ad = sB + (uint32_t)row*128u + (col ^ (((uint32_t)row&7u)*16u));
                LDSM4(bfr[g][0],bfr[g][1],bfr[g][2],bfr[g][3], ad);
            }
#pragma unroll
            for (int mi = 0; mi < 4; ++mi)
#pragma unroll
                for (int nj = 0; nj < 8; ++nj){
                    const int g = nj>>1, hf = nj&1;
                    MMAH(acc[mi][nj], a[mi][0],a[mi][1],a[mi][2],a[mi][3],
                         bfr[g][hf], bfr[g][hf+2]);
                }
        }
        __syncthreads();
    }

    const int mwb = m0 + wm*64, nwb = n0 + wn*64;
#pragma unroll
    for (int mi = 0; mi < 4; ++mi)
#pragma unroll
    for (int nj = 0; nj < 8; ++nj){
        const int col = nwb + nj*8 + (lane&3)*2;
        const float2 bb = *(const float2*)&bias[col];
#pragma unroll
        for (int h = 0; h < 2; ++h){
            const int row = mwb + mi*16 + (lane>>2) + h*8;
            float x0 = acc[mi][nj][h*2+0] + bb.x;
            float x1 = acc[mi][nj][h*2+1] + bb.y;
            if (mode == 1){
                float2 rr = *(const float2*)&Rres[(size_t)row*N + col];
                x0 += rr.x; x1 += rr.y;
            }
            if (mode == 2){
                x0 = fmaxf(x0, 0.f); x1 = fmaxf(x1, 0.f);
                *(uint32_t*)&Ch[(size_t)row*N + col] = hpack2(__float2half(x0), __float2half(x1));
            } else {
                *(float2*)&Cf[(size_t)row*N + col] = make_float2(x0, x1);
            }
        }
    }
}

// ---- window-3 attention on fused qkv [M,3072]; fp16 ctx out ----
__global__ __launch_bounds__(512) void attn_kernel(
    const float* __restrict__ qkv, const unsigned char* __restrict__ mask,
    __half* __restrict__ ch)
{
    const int bl = blockIdx.x, b = bl>>12, l = bl&4095;
    const int wid = threadIdx.x>>5, lane = threadIdx.x&31;
    const size_t qb = (size_t)bl*3072 + wid*64;
    const float q0 = qkv[qb+lane], q1 = qkv[qb+lane+32];
    float sc[3]; int lks[3];
#pragma unroll
    for (int w = 0; w < 3; w++){
        int lk = l + w - 1;
        bool inb = (lk >= 0) && (lk < Ll);
        int lkc = lk < 0 ? 0 : (lk > Ll-1 ? Ll-1 : lk);
        lks[w] = lkc;
        bool ok = inb && (mask[(b<<12)+lkc] == 0);
        const size_t kb = (size_t)((b<<12)+lkc)*3072 + 1024 + wid*64;
        float d = q0*qkv[kb+lane] + q1*qkv[kb+lane+32];
#pragma unroll
        for (int o = 16; o; o >>= 1) d += __shfl_xor_sync(0xffffffffu, d, o);
        sc[w] = ok ? d*0.125f : -1e30f;
    }
    float m = fmaxf(sc[0], fmaxf(sc[1], sc[2]));
    float e0 = expf(sc[0]-m), e1 = expf(sc[1]-m), e2 = expf(sc[2]-m);
    float inv = 1.f/(e0+e1+e2);
    float a0 = e0*inv, a1 = e1*inv, a2 = e2*inv;
    float c0 = 0.f, c1 = 0.f;
#pragma unroll
    for (int w = 0; w < 3; w++){
        const float aw = (w==0)?a0:(w==1?a1:a2);
        const size_t vb = (size_t)((b<<12)+lks[w])*3072 + 2048 + wid*64;
        c0 += aw*qkv[vb+lane]; c1 += aw*qkv[vb+lane+32];
    }
    const size_t ob = (size_t)bl*Dd + wid*64;
    ch[ob+lane]    = __float2half(c0);
    ch[ob+lane+32] = __float2half(c1);
}

__global__ __launch_bounds__(256) void ln_kernel(
    const float* __restrict__ X, const float* __restrict__ gam,
    const float* __restrict__ bet, float* __restrict__ Y, __half* __restrict__ Yh)
{
    const int row = blockIdx.x, tid = threadIdx.x;
    float4 vv = ((const float4*)(X + (size_t)row*Dd))[tid];
    float s = vv.x+vv.y+vv.z+vv.w;
    float ss = vv.x*vv.x+vv.y*vv.y+vv.z*vv.z+vv.w*vv.w;
#pragma unroll
    for (int o = 16; o; o >>= 1){
        s += __shfl_xor_sync(0xffffffffu, s, o);
        ss += __shfl_xor_sync(0xffffffffu, ss, o);
    }
    __shared__ float sh_s[8], sh_ss[8];
    const int w = tid>>5, lane = tid&31;
    if (lane == 0){ sh_s[w]=s; sh_ss[w]=ss; }
    __syncthreads();
    s = 0.f; ss = 0.f;
#pragma unroll
    for (int i = 0; i < 8; i++){ s += sh_s[i]; ss += sh_ss[i]; }
    const float mean = s*(1.f/Dd);
    const float var = ss*(1.f/Dd) - mean*mean;
    const float rstd = rsqrtf(var + 1e-5f);
    float4 g4 = ((const float4*)gam)[tid], b4 = ((const float4*)bet)[tid];
    float4 o;
    o.x=(vv.x-mean)*rstd*g4.x+b4.x; o.y=(vv.y-mean)*rstd*g4.y+b4.y;
    o.z=(vv.z-mean)*rstd*g4.z+b4.z; o.w=(vv.w-mean)*rstd*g4.w+b4.w;
    ((float4*)(Y + (size_t)row*Dd))[tid] = o;
    if (Yh){
        size_t i = (size_t)row*(Dd/4) + tid;
        ((uint32_t*)Yh)[i*2]   = hpack2(__float2half(o.x), __float2half(o.y));
        ((uint32_t*)Yh)[i*2+1] = hpack2(__float2half(o.z), __float2half(o.w));
    }
}

extern "C" void kernel_launch(void* const* d_in, const int* in_sizes, int n_in,
                              void* d_out, int out_size)
{
    const float* X = (const float*)d_in[0];
    const unsigned char* mask = (const unsigned char*)d_in[1];
    const float* pe = (const float*)d_in[2];
    const float *Wq=(const float*)d_in[3], *Wk=(const float*)d_in[4], *Wv=(const float*)d_in[5];
    const float *bq=(const float*)d_in[6], *bk=(const float*)d_in[7], *bv=(const float*)d_in[8];
    const float *Wo=(const float*)d_in[9], *bo=(const float*)d_in[10];
    const float *g1=(const float*)d_in[11], *be1=(const float*)d_in[12];
    const float *W1=(const float*)d_in[13], *b1=(const float*)d_in[14];
    const float *W2=(const float*)d_in[15], *b2=(const float*)d_in[16];
    const float *g2=(const float*)d_in[17], *be2=(const float*)d_in[18];
    float* out = (float*)d_out;

    float *xp,*qkv,*y1,*x1,*bqkv;
    __half *xph,*ch,*x1h,*hh;
    __half *wqkvh,*woh,*w1h,*w2h;
    cudaGetSymbolAddress((void**)&xp,g_xp);     cudaGetSymbolAddress((void**)&qkv,g_qkv);
    cudaGetSymbolAddress((void**)&y1,g_y1);     cudaGetSymbolAddress((void**)&x1,g_x1);
    cudaGetSymbolAddress((void**)&bqkv,g_bqkv);
    cudaGetSymbolAddress((void**)&xph,g_xph);   cudaGetSymbolAddress((void**)&ch,g_ch);
    cudaGetSymbolAddress((void**)&x1h,g_x1h);   cudaGetSymbolAddress((void**)&hh,g_hh);
    cudaGetSymbolAddress((void**)&wqkvh,g_wqkvh);
    cudaGetSymbolAddress((void**)&woh,g_woh);
    cudaGetSymbolAddress((void**)&w1h,g_w1h);
    cudaGetSymbolAddress((void**)&w2h,g_w2h);

    const size_t sm = STAGES*STGB;   // 96KB
    cudaFuncSetAttribute(tgemm, cudaFuncAttributeMaxDynamicSharedMemorySize, (int)sm);

    addpe_split<<<8192,256>>>(X, pe, xp, xph);
    // fused QKV weight: rows 0-1023 = Wq^T, 1024-2047 = Wk^T, 2048-3071 = Wv^T
    wtrans<<<dim3(32,32),256>>>(Wq, Dd, Dd, wqkvh);
    wtrans<<<dim3(32,32),256>>>(Wk, Dd, Dd, wqkvh + 1024*1024);
    wtrans<<<dim3(32,32),256>>>(Wv, Dd, Dd, wqkvh + 2048*1024);
    wtrans<<<dim3(32,32),256>>>(Wo, Dd, Dd, woh);
    wtrans<<<dim3(128,32),256>>>(W1, Dd, FFD, w1h);
    wtrans<<<dim3(32,128),256>>>(W2, FFD, Dd, w2h);
    catb3<<<12,256>>>(bq, bk, bv, bqkv);

    const dim3 gQKV(3072/128, Mrows/128);  // (24, 256)
    const dim3 gDD(Dd/128, Mrows/128);     // (8, 256)
    const dim3 gDF(FFD/128, Mrows/128);    // (32, 256)

    tgemm<<<gQKV,128,sm>>>(xph, wqkvh, bqkv, nullptr, qkv, nullptr, Dd, 3072, 0);

    attn_kernel<<<Mrows,512>>>(qkv, mask, ch);

    tgemm<<<gDD,128,sm>>>(ch, woh, bo, xp, y1, nullptr, Dd, Dd, 1);
    ln_kernel<<<Mrows,256>>>(y1, g1, be1, x1, x1h);

    tgemm<<<gDF,128,sm>>>(x1h, w1h, b1, nullptr, nullptr, hh, Dd, FFD, 2);
    tgemm<<<gDD,128,sm>>>(hh, w2h, b2, x1, y1, nullptr, FFD, Dd, 1);
    ln_kernel<<<Mrows,256>>>(y1, g2, be2, out, nullptr);
}

// round 10
// speedup vs baseline: 8.1917x; 1.0065x over previous
#include <cuda_runtime.h>
#include <cuda_fp16.h>
#include <cstdint>

#define Bb 8
#define Ll 4096
#define Dd 1024
#define FFD 4096
#define Mrows (Bb*Ll)
#define NE   (Mrows*Dd)
#define NEFF (Mrows*FFD)

__device__ float g_xp[NE];                 // X + pe (fp32, residual)
__device__ float g_y1[NE], g_x1[NE];
__device__ float g_bqkv[3072];
__device__ __half g_qkvh[Mrows*3072];      // fused QKV output (fp16)
__device__ __half g_xph[NE], g_ch[NE], g_x1h[NE], g_hh[NEFF];
__device__ __half g_wqkvh[3*Dd*Dd];
__device__ __half g_woh[Dd*Dd];
__device__ __half g_w1h[Dd*FFD];
__device__ __half g_w2h[FFD*Dd];

__device__ __forceinline__ uint32_t smem_u32(const void* p){
    uint32_t a; asm("{ .reg .u64 t; cvta.to.shared.u64 t, %1; cvt.u32.u64 %0, t; }":"=r"(a):"l"(p)); return a;
}
__device__ __forceinline__ uint32_t hpack2(__half a, __half b){
    return (uint32_t)__half_as_ushort(a) | ((uint32_t)__half_as_ushort(b) << 16);
}

#define LDSM4(r0,r1,r2,r3,ad) \
    asm volatile("ldmatrix.sync.aligned.m8n8.x4.shared.b16 {%0,%1,%2,%3}, [%4];" \
        : "=r"(r0),"=r"(r1),"=r"(r2),"=r"(r3) : "r"(ad))

#define MMAH(d,a0,a1,a2,a3,b0,b1) \
    asm volatile("mma.sync.aligned.m16n8k16.row.col.f32.f16.f16.f32 " \
        "{%0,%1,%2,%3},{%4,%5,%6,%7},{%8,%9},{%0,%1,%2,%3};" \
        : "+f"((d)[0]),"+f"((d)[1]),"+f"((d)[2]),"+f"((d)[3]) \
        : "r"(a0),"r"(a1),"r"(a2),"r"(a3),"r"(b0),"r"(b1))

#define CPA16(sd,gp) asm volatile("cp.async.cg.shared.global [%0], [%1], 16;"::"r"(sd),"l"(gp):"memory")

__global__ __launch_bounds__(256) void addpe_split(
    const float* __restrict__ X, const float* __restrict__ pe,
    float* __restrict__ xp, __half* __restrict__ xh)
{
    const size_t n4 = (size_t)NE/4, pe4 = (size_t)Ll*Dd/4;
    for (size_t i = (size_t)blockIdx.x*blockDim.x+threadIdx.x; i < n4; i += (size_t)gridDim.x*blockDim.x){
        float4 a = ((const float4*)X)[i]; float4 p = ((const float4*)pe)[i % pe4];
        a.x+=p.x; a.y+=p.y; a.z+=p.z; a.w+=p.w;
        ((float4*)xp)[i] = a;
        ((uint32_t*)xh)[i*2]   = hpack2(__float2half(a.x), __float2half(a.y));
        ((uint32_t*)xh)[i*2+1] = hpack2(__float2half(a.z), __float2half(a.w));
    }
}

__global__ __launch_bounds__(256) void wtrans(
    const float* __restrict__ W, int K, int N, __half* __restrict__ Th)
{
    __shared__ float t[32][33];
    const int bn = blockIdx.x*32, bk = blockIdx.y*32;
    const int tx = threadIdx.x&31, ty = threadIdx.x>>5;
#pragma unroll
    for (int r = 0; r < 32; r += 8) t[ty+r][tx] = W[(size_t)(bk+ty+r)*N + bn+tx];
    __syncthreads();
#pragma unroll
    for (int r = 0; r < 32; r += 8){
        Th[(size_t)(bn+ty+r)*K + bk+tx] = __float2half(t[tx][ty+r]);
    }
}

__global__ __launch_bounds__(256) void catb3(
    const float* __restrict__ a, const float* __restrict__ b,
    const float* __restrict__ c, float* __restrict__ o)
{
    int i = blockIdx.x*256 + threadIdx.x;
    if (i < 1024) o[i] = a[i];
    else if (i < 2048) o[i] = b[i-1024];
    else if (i < 3072) o[i] = c[i-2048];
}

// ---- HMMA GEMM: D[M,N] = A[M,K] @ B[N,K]^T, fp16, fp32 accum ----
// BM=128 BN=128 BK=64, 4 warps (2x2), warp tile 64x64,
// 3 stages x 32KB = 96KB -> 2 CTAs/SM
#define STAGES 3
#define STGB 32768

__device__ __forceinline__ void load_op(uint32_t sdst, const __half* __restrict__ g,
                                        int ldk, int row0, int k0, int tid)
{
    const __half* gb = g + (size_t)row0*ldk + k0;
#pragma unroll
    for (int t = 0; t < 8; ++t){
        int idx = t*128 + tid;
        int row = idx >> 3, j = idx & 7;
        uint32_t so = (uint32_t)row*128u + (((uint32_t)j*16u) ^ (((uint32_t)row&7u)*16u));
        CPA16(sdst + so, gb + (size_t)row*ldk + j*8);
    }
}

// mode 0: bias->Cf ; 1: bias+R->Cf ; 2: relu(bias)->Ch ; 3: bias->Ch
__global__ void __launch_bounds__(128,2) tgemm(
    const __half* __restrict__ Ah, const __half* __restrict__ Bh,
    const float* __restrict__ bias, const float* __restrict__ Rres,
    float* __restrict__ Cf, __half* __restrict__ Ch,
    int K, int N, int mode)
{
    extern __shared__ char smem[];
    const uint32_t sb = smem_u32(smem);
    const int tid = threadIdx.x, wid = tid>>5, lane = tid&31;
    const int wm = wid & 1, wn = wid >> 1;     // 2x2 warps, 64x64 tiles
    const int m0 = blockIdx.y*128, n0 = blockIdx.x*128;
    const int T = K >> 6;

    float acc[4][8][4];
#pragma unroll
    for (int a=0;a<4;a++)
#pragma unroll
    for (int b=0;b<8;b++)
#pragma unroll
    for (int c=0;c<4;c++) acc[a][b][c]=0.f;

#pragma unroll
    for (int it = 0; it < STAGES-1; ++it){
        const int kk = it*64;
        load_op(sb + it*STGB,          Ah, K, m0, kk, tid);
        load_op(sb + it*STGB + 16384,  Bh, K, n0, kk, tid);
        asm volatile("cp.async.commit_group;":::"memory");
    }

    const int r16 = lane & 15, cg = lane >> 4;
    for (int it = 0; it < T; ++it){
        if (it == T-1) asm volatile("cp.async.wait_group 0;":::"memory");
        else           asm volatile("cp.async.wait_group %0;"::"n"(STAGES-2):"memory");
        __syncthreads();          // also orders reuse of slot (it%3) by next loads
        if (it + STAGES-1 < T){
            const int it2 = it + STAGES-1, kk = it2*64;
            const uint32_t slot = sb + (it2 % STAGES)*STGB;
            load_op(slot,         Ah, K, m0, kk, tid);
            load_op(slot + 16384, Bh, K, n0, kk, tid);
            asm volatile("cp.async.commit_group;":::"memory");
        }
        const uint32_t sA = sb + (it % STAGES)*STGB, sB = sA + 16384u;
#pragma unroll
        for (int kk = 0; kk < 4; ++kk){
            const uint32_t col = (uint32_t)kk*32u + (uint32_t)cg*16u;
            uint32_t a[4][4], bfr[4][4];
#pragma unroll
            for (int mi = 0; mi < 4; ++mi){
                int row = wm*64 + mi*16 + r16;
                uint32_t ad = sA + (uint32_t)row*128u + (col ^ (((uint32_t)row&7u)*16u));
                LDSM4(a[mi][0],a[mi][1],a[mi][2],a[mi][3], ad);
            }
#pragma unroll
            for (int g = 0; g < 4; ++g){
                int row = wn*64 + g*16 + r16;
                uint32_t ad = sB + (uint32_t)row*128u + (col ^ (((uint32_t)row&7u)*16u));
                LDSM4(bfr[g][0],bfr[g][1],bfr[g][2],bfr[g][3], ad);
            }
#pragma unroll
            for (int mi = 0; mi < 4; ++mi)
#pragma unroll
                for (int nj = 0; nj < 8; ++nj){
                    const int g = nj>>1, hf = nj&1;
                    MMAH(acc[mi][nj], a[mi][0],a[mi][1],a[mi][2],a[mi][3],
                         bfr[g][hf], bfr[g][hf+2]);
                }
        }
        // no trailing __syncthreads: top-of-loop barrier suffices with 3 stages
    }

    const int mwb = m0 + wm*64, nwb = n0 + wn*64;
#pragma unroll
    for (int mi = 0; mi < 4; ++mi)
#pragma unroll
    for (int nj = 0; nj < 8; ++nj){
        const int col = nwb + nj*8 + (lane&3)*2;
        const float2 bb = *(const float2*)&bias[col];
#pragma unroll
        for (int h = 0; h < 2; ++h){
            const int row = mwb + mi*16 + (lane>>2) + h*8;
            float x0 = acc[mi][nj][h*2+0] + bb.x;
            float x1 = acc[mi][nj][h*2+1] + bb.y;
            if (mode == 1){
                float2 rr = *(const float2*)&Rres[(size_t)row*N + col];
                x0 += rr.x; x1 += rr.y;
            }
            if (mode >= 2){
                if (mode == 2){ x0 = fmaxf(x0, 0.f); x1 = fmaxf(x1, 0.f); }
                *(uint32_t*)&Ch[(size_t)row*N + col] = hpack2(__float2half(x0), __float2half(x1));
            } else {
                *(float2*)&Cf[(size_t)row*N + col] = make_float2(x0, x1);
            }
        }
    }
}

// ---- window-3 attention on fused fp16 qkv [M,3072]; fp16 ctx out ----
__global__ __launch_bounds__(512) void attn_kernel(
    const __half* __restrict__ qkv, const unsigned char* __restrict__ mask,
    __half* __restrict__ ch)
{
    const int bl = blockIdx.x, b = bl>>12, l = bl&4095;
    const int wid = threadIdx.x>>5, lane = threadIdx.x&31;
    const size_t qb = (size_t)bl*3072 + wid*64;
    const float2 qf = __half22float2(((const __half2*)(qkv + qb))[lane]);
    float sc[3]; int lks[3];
#pragma unroll
    for (int w = 0; w < 3; w++){
        int lk = l + w - 1;
        bool inb = (lk >= 0) && (lk < Ll);
        int lkc = lk < 0 ? 0 : (lk > Ll-1 ? Ll-1 : lk);
        lks[w] = lkc;
        bool ok = inb && (mask[(b<<12)+lkc] == 0);
        const size_t kb = (size_t)((b<<12)+lkc)*3072 + 1024 + wid*64;
        const float2 kf = __half22float2(((const __half2*)(qkv + kb))[lane]);
        float d = qf.x*kf.x + qf.y*kf.y;
#pragma unroll
        for (int o = 16; o; o >>= 1) d += __shfl_xor_sync(0xffffffffu, d, o);
        sc[w] = ok ? d*0.125f : -1e30f;
    }
    float m = fmaxf(sc[0], fmaxf(sc[1], sc[2]));
    float e0 = expf(sc[0]-m), e1 = expf(sc[1]-m), e2 = expf(sc[2]-m);
    float inv = 1.f/(e0+e1+e2);
    float a0 = e0*inv, a1 = e1*inv, a2 = e2*inv;
    float c0 = 0.f, c1 = 0.f;
#pragma unroll
    for (int w = 0; w < 3; w++){
        const float aw = (w==0)?a0:(w==1?a1:a2);
        const size_t vb = (size_t)((b<<12)+lks[w])*3072 + 2048 + wid*64;
        const float2 vf = __half22float2(((const __half2*)(qkv + vb))[lane]);
        c0 += aw*vf.x; c1 += aw*vf.y;
    }
    const size_t ob = (size_t)bl*Dd + wid*64;
    ((__half2*)(ch + ob))[lane] = __floats2half2_rn(c0, c1);
}

__global__ __launch_bounds__(256) void ln_kernel(
    const float* __restrict__ X, const float* __restrict__ gam,
    const float* __restrict__ bet, float* __restrict__ Y, __half* __restrict__ Yh)
{
    const int row = blockIdx.x, tid = threadIdx.x;
    float4 vv = ((const float4*)(X + (size_t)row*Dd))[tid];
    float s = vv.x+vv.y+vv.z+vv.w;
    float ss = vv.x*vv.x+vv.y*vv.y+vv.z*vv.z+vv.w*vv.w;
#pragma unroll
    for (int o = 16; o; o >>= 1){
        s += __shfl_xor_sync(0xffffffffu, s, o);
        ss += __shfl_xor_sync(0xffffffffu, ss, o);
    }
    __shared__ float sh_s[8], sh_ss[8];
    const int w = tid>>5, lane = tid&31;
    if (lane == 0){ sh_s[w]=s; sh_ss[w]=ss; }
    __syncthreads();
    s = 0.f; ss = 0.f;
#pragma unroll
    for (int i = 0; i < 8; i++){ s += sh_s[i]; ss += sh_ss[i]; }
    const float mean = s*(1.f/Dd);
    const float var = ss*(1.f/Dd) - mean*mean;
    const float rstd = rsqrtf(var + 1e-5f);
    float4 g4 = ((const float4*)gam)[tid], b4 = ((const float4*)bet)[tid];
    float4 o;
    o.x=(vv.x-mean)*rstd*g4.x+b4.x; o.y=(vv.y-mean)*rstd*g4.y+b4.y;
    o.z=(vv.z-mean)*rstd*g4.z+b4.z; o.w=(vv.w-mean)*rstd*g4.w+b4.w;
    ((float4*)(Y + (size_t)row*Dd))[tid] = o;
    if (Yh){
        size_t i = (size_t)row*(Dd/4) + tid;
        ((uint32_t*)Yh)[i*2]   = hpack2(__float2half(o.x), __float2half(o.y));
        ((uint32_t*)Yh)[i*2+1] = hpack2(__float2half(o.z), __float2half(o.w));
    }
}

extern "C" void kernel_launch(void* const* d_in, const int* in_sizes, int n_in,
                              void* d_out, int out_size)
{
    const float* X = (const float*)d_in[0];
    const unsigned char* mask = (const unsigned char*)d_in[1];
    const float* pe = (const float*)d_in[2];
    const float *Wq=(const float*)d_in[3], *Wk=(const float*)d_in[4], *Wv=(const float*)d_in[5];
    const float *bq=(const float*)d_in[6], *bk=(const float*)d_in[7], *bv=(const float*)d_in[8];
    const float *Wo=(const float*)d_in[9], *bo=(const float*)d_in[10];
    const float *g1=(const float*)d_in[11], *be1=(const float*)d_in[12];
    const float *W1=(const float*)d_in[13], *b1=(const float*)d_in[14];
    const float *W2=(const float*)d_in[15], *b2=(const float*)d_in[16];
    const float *g2=(const float*)d_in[17], *be2=(const float*)d_in[18];
    float* out = (float*)d_out;

    float *xp,*y1,*x1,*bqkv;
    __half *qkvh,*xph,*ch,*x1h,*hh;
    __half *wqkvh,*woh,*w1h,*w2h;
    cudaGetSymbolAddress((void**)&xp,g_xp);
    cudaGetSymbolAddress((void**)&y1,g_y1);     cudaGetSymbolAddress((void**)&x1,g_x1);
    cudaGetSymbolAddress((void**)&bqkv,g_bqkv); cudaGetSymbolAddress((void**)&qkvh,g_qkvh);
    cudaGetSymbolAddress((void**)&xph,g_xph);   cudaGetSymbolAddress((void**)&ch,g_ch);
    cudaGetSymbolAddress((void**)&x1h,g_x1h);   cudaGetSymbolAddress((void**)&hh,g_hh);
    cudaGetSymbolAddress((void**)&wqkvh,g_wqkvh);
    cudaGetSymbolAddress((void**)&woh,g_woh);
    cudaGetSymbolAddress((void**)&w1h,g_w1h);
    cudaGetSymbolAddress((void**)&w2h,g_w2h);

    const size_t sm = STAGES*STGB;   // 96KB
    cudaFuncSetAttribute(tgemm, cudaFuncAttributeMaxDynamicSharedMemorySize, (int)sm);

    const dim3 gQKV(3072/128, Mrows/128);  // (24, 256)
    const dim3 gDD(Dd/128, Mrows/128);     // (8, 256)
    const dim3 gDF(FFD/128, Mrows/128);    // (32, 256)

    // launches 1-5: exactly the QKV-GEMM dependencies, so tgemm(QKV) is launch #6
    addpe_split<<<8192,256>>>(X, pe, xp, xph);                  // 1
    wtrans<<<dim3(32,32),256>>>(Wq, Dd, Dd, wqkvh);             // 2
    wtrans<<<dim3(32,32),256>>>(Wk, Dd, Dd, wqkvh + 1024*1024); // 3
    wtrans<<<dim3(32,32),256>>>(Wv, Dd, Dd, wqkvh + 2048*1024); // 4
    catb3<<<12,256>>>(bq, bk, bv, bqkv);                        // 5

    tgemm<<<gQKV,128,sm>>>(xph, wqkvh, bqkv, nullptr, nullptr, qkvh, Dd, 3072, 3); // 6 (profiled)

    wtrans<<<dim3(32,32),256>>>(Wo, Dd, Dd, woh);
    wtrans<<<dim3(128,32),256>>>(W1, Dd, FFD, w1h);
    wtrans<<<dim3(32,128),256>>>(W2, FFD, Dd, w2h);

    attn_kernel<<<Mrows,512>>>(qkvh, mask, ch);

    tgemm<<<gDD,128,sm>>>(ch, woh, bo, xp, y1, nullptr, Dd, Dd, 1);
    ln_kernel<<<Mrows,256>>>(y1, g1, be1, x1, x1h);

    tgemm<<<gDF,128,sm>>>(x1h, w1h, b1, nullptr, nullptr, hh, Dd, FFD, 2);
    tgemm<<<gDD,128,sm>>>(hh, w2h, b2, x1, y1, nullptr, FFD, Dd, 1);
    ln_kernel<<<Mrows,256>>>(y1, g2, be2, out, nullptr);
}